// round 1
// baseline (speedup 1.0000x reference)
#include <cuda_runtime.h>

#define NB   2048
#define NN   64
#define DD   128
#define NPAD 132
#define PCH  36
#define NEG_BIG (-9000000000000000.0f)

__global__ void __launch_bounds__(256, 2)
star_agg_kernel(const float* __restrict__ hidden,
                const int*   __restrict__ adj,
                const float* __restrict__ mask,
                const float* __restrict__ a0,
                const float* __restrict__ a1,
                const float* __restrict__ a2,
                const float* __restrict__ a3,
                const float* __restrict__ q1,
                const float* __restrict__ k1,
                const float* __restrict__ q2,
                const float* __restrict__ k2,
                const float* __restrict__ wlin,
                float* __restrict__ outp,
                float* __restrict__ starp)
{
    extern __shared__ float sm[];
    float* S    = sm;                       // 64*132 sate
    float* T    = S + NN * NPAD;            // 64*132 scratch
    float* P    = T + NN * NPAD;            // 4*64*36 scaled table / W staging
    float* A    = P + 4 * 64 * PCH;         // 4*128 edge-type vectors
    float* STAR = A + 512;                  // 128
    float* V1   = STAR + 128;               // 128
    float* V2   = V1 + 128;                 // 128
    float* MS   = V2 + 128;                 // 64
    float* BR   = MS + 64;                  // 64
    unsigned char* ADJ = (unsigned char*)(BR + 64);  // 4096 B

    const int tid  = threadIdx.x;
    const int lane = tid & 31;
    const int warp = tid >> 5;
    const int b    = blockIdx.x;
    const int rowBase = warp * 8;

    const float* hg = hidden + (size_t)b * (NN * DD);
    const int*   ag = adj    + (size_t)b * (NN * NN);

    // ---- load hidden -> S (sate starts as hidden), adj, a_k, mask ----
    for (int idx = tid; idx < NN * DD / 4; idx += 256) {
        int i  = idx >> 5;
        int c4 = (idx & 31) << 2;
        float4 v = reinterpret_cast<const float4*>(hg)[idx];
        *reinterpret_cast<float4*>(&S[i * NPAD + c4]) = v;
    }
    for (int idx = tid; idx < NN * NN; idx += 256)
        ADJ[idx] = (unsigned char)ag[idx];
    if (tid < 128) {
        A[tid]       = a0[tid];
        A[128 + tid] = a1[tid];
        A[256 + tid] = a2[tid];
        A[384 + tid] = a3[tid];
    }
    if (tid < 64) MS[tid] = mask[b * NN + tid];
    __syncthreads();

    // ---- star = masked mean over nodes ----
    if (tid < 128) {
        float acc = 0.f, msum = 0.f;
        #pragma unroll 8
        for (int i = 0; i < NN; i++) {
            acc  += S[i * NPAD + tid] * MS[i];
            msum += MS[i];
        }
        STAR[tid] = acc / msum;
    }
    __syncthreads();

    const float RSQ = 0.088388347648318447f;  // 1/sqrt(128)

    for (int step = 0; step < 2; step++) {
        // ================= local_agg =================
        // warp handles rows rowBase..rowBase+7; lane handles cols j=lane, lane+32
        float acc0[8], acc1[8];
        int   off0[8], off1[8];
        #pragma unroll
        for (int r = 0; r < 8; r++) {
            acc0[r] = 0.f; acc1[r] = 0.f;
            int ka = ADJ[(rowBase + r) * 64 + lane];
            int kb = ADJ[(rowBase + r) * 64 + lane + 32];
            int sa = (ka == 0) ? 0 : ka - 1;
            int sb = (kb == 0) ? 0 : kb - 1;
            off0[r] = (sa * 64 + lane) * PCH;
            off1[r] = (sb * 64 + lane + 32) * PCH;
        }
        for (int ch = 0; ch < 4; ch++) {
            const int d0 = ch * 32;
            __syncthreads();
            // build P[k][j][dd] = a_k[d0+dd] * s[j][d0+dd]
            for (int idx = tid; idx < 4 * 64 * 32; idx += 256) {
                int k  = idx >> 11;
                int j  = (idx >> 5) & 63;
                int dd = idx & 31;
                P[(k * 64 + j) * PCH + dd] = A[k * 128 + d0 + dd] * S[j * NPAD + d0 + dd];
            }
            __syncthreads();
            #pragma unroll
            for (int dd = 0; dd < 32; dd += 4) {
                #pragma unroll
                for (int r = 0; r < 8; r++) {
                    float4 si = *reinterpret_cast<const float4*>(&S[(rowBase + r) * NPAD + d0 + dd]);
                    float4 p0 = *reinterpret_cast<const float4*>(&P[off0[r] + dd]);
                    float4 p1 = *reinterpret_cast<const float4*>(&P[off1[r] + dd]);
                    acc0[r] += si.x * p0.x + si.y * p0.y + si.z * p0.z + si.w * p0.w;
                    acc1[r] += si.x * p1.x + si.y * p1.y + si.z * p1.z + si.w * p1.w;
                }
            }
        }
        // leaky + mask + row softmax (64 values across warp: 2 per lane)
        float att0[8], att1[8];
        #pragma unroll
        for (int r = 0; r < 8; r++) {
            int i = rowBase + r;
            int ka = ADJ[i * 64 + lane];
            int kb = ADJ[i * 64 + lane + 32];
            float dv0 = acc0[r], dv1 = acc1[r];
            float l0 = (ka == 0) ? NEG_BIG : (dv0 >= 0.f ? dv0 : 0.2f * dv0);
            float l1 = (kb == 0) ? NEG_BIG : (dv1 >= 0.f ? dv1 : 0.2f * dv1);
            float m = fmaxf(l0, l1);
            #pragma unroll
            for (int o = 16; o > 0; o >>= 1) m = fmaxf(m, __shfl_xor_sync(0xffffffffu, m, o));
            float e0 = __expf(l0 - m);
            float e1 = __expf(l1 - m);
            float sE = e0 + e1;
            #pragma unroll
            for (int o = 16; o > 0; o >>= 1) sE += __shfl_xor_sync(0xffffffffu, sE, o);
            float inv = 1.f / sE;
            att0[r] = e0 * inv;
            att1[r] = e1 * inv;
        }
        // T = att @ S  (4 rows jointly share each S[j] load)
        #pragma unroll
        for (int g = 0; g < 2; g++) {
            float4 o0 = {0,0,0,0}, o1 = {0,0,0,0}, o2 = {0,0,0,0}, o3 = {0,0,0,0};
            for (int j = 0; j < 32; j++) {
                float4 sj = *reinterpret_cast<const float4*>(&S[j * NPAD + lane * 4]);
                float w0 = __shfl_sync(0xffffffffu, att0[g * 4 + 0], j);
                float w1 = __shfl_sync(0xffffffffu, att0[g * 4 + 1], j);
                float w2 = __shfl_sync(0xffffffffu, att0[g * 4 + 2], j);
                float w3 = __shfl_sync(0xffffffffu, att0[g * 4 + 3], j);
                o0.x += w0*sj.x; o0.y += w0*sj.y; o0.z += w0*sj.z; o0.w += w0*sj.w;
                o1.x += w1*sj.x; o1.y += w1*sj.y; o1.z += w1*sj.z; o1.w += w1*sj.w;
                o2.x += w2*sj.x; o2.y += w2*sj.y; o2.z += w2*sj.z; o2.w += w2*sj.w;
                o3.x += w3*sj.x; o3.y += w3*sj.y; o3.z += w3*sj.z; o3.w += w3*sj.w;
            }
            for (int j = 0; j < 32; j++) {
                float4 sj = *reinterpret_cast<const float4*>(&S[(j + 32) * NPAD + lane * 4]);
                float w0 = __shfl_sync(0xffffffffu, att1[g * 4 + 0], j);
                float w1 = __shfl_sync(0xffffffffu, att1[g * 4 + 1], j);
                float w2 = __shfl_sync(0xffffffffu, att1[g * 4 + 2], j);
                float w3 = __shfl_sync(0xffffffffu, att1[g * 4 + 3], j);
                o0.x += w0*sj.x; o0.y += w0*sj.y; o0.z += w0*sj.z; o0.w += w0*sj.w;
                o1.x += w1*sj.x; o1.y += w1*sj.y; o1.z += w1*sj.z; o1.w += w1*sj.w;
                o2.x += w2*sj.x; o2.y += w2*sj.y; o2.z += w2*sj.z; o2.w += w2*sj.w;
                o3.x += w3*sj.x; o3.y += w3*sj.y; o3.z += w3*sj.z; o3.w += w3*sj.w;
            }
            *reinterpret_cast<float4*>(&T[(rowBase + g * 4 + 0) * NPAD + lane * 4]) = o0;
            *reinterpret_cast<float4*>(&T[(rowBase + g * 4 + 1) * NPAD + lane * 4]) = o1;
            *reinterpret_cast<float4*>(&T[(rowBase + g * 4 + 2) * NPAD + lane * 4]) = o2;
            *reinterpret_cast<float4*>(&T[(rowBase + g * 4 + 3) * NPAD + lane * 4]) = o3;
        }
        __syncthreads();

        // ================ alpha update ================
        // V1 = k1^T @ star ; V2 = q1 @ V1   (collapses q@k^T to one vector)
        if (tid < 128) {
            float acc = 0.f;
            #pragma unroll 8
            for (int c = 0; c < 128; c++) acc += STAR[c] * k1[c * 128 + tid];
            V1[tid] = acc;
        }
        __syncthreads();
        if (tid < 128) {
            float acc = 0.f;
            const float4* qr = reinterpret_cast<const float4*>(q1 + tid * 128);
            #pragma unroll 8
            for (int d4 = 0; d4 < 32; d4++) {
                float4 qv = qr[d4];
                float4 vv = *reinterpret_cast<const float4*>(&V1[d4 * 4]);
                acc += qv.x * vv.x + qv.y * vv.y + qv.z * vv.z + qv.w * vv.w;
            }
            V2[tid] = acc;
        }
        __syncthreads();
        // alpha_i = (T[i] . V2)/sqrt(d); S = (1-alpha)T + alpha*star
        #pragma unroll
        for (int r = 0; r < 8; r++) {
            int i = rowBase + r;
            float4 tv = *reinterpret_cast<const float4*>(&T[i * NPAD + lane * 4]);
            float4 qv = *reinterpret_cast<const float4*>(&V2[lane * 4]);
            float part = tv.x * qv.x + tv.y * qv.y + tv.z * qv.z + tv.w * qv.w;
            #pragma unroll
            for (int o = 16; o > 0; o >>= 1) part += __shfl_xor_sync(0xffffffffu, part, o);
            float al = part * RSQ;
            float4 st = *reinterpret_cast<const float4*>(&STAR[lane * 4]);
            float4 ns;
            ns.x = (1.f - al) * tv.x + al * st.x;
            ns.y = (1.f - al) * tv.y + al * st.y;
            ns.z = (1.f - al) * tv.z + al * st.z;
            ns.w = (1.f - al) * tv.w + al * st.w;
            *reinterpret_cast<float4*>(&S[i * NPAD + lane * 4]) = ns;
        }
        __syncthreads();

        // ================ beta update ================
        if (tid < 128) {
            float acc = 0.f;
            #pragma unroll 8
            for (int c = 0; c < 128; c++) acc += STAR[c] * q2[c * 128 + tid];
            V1[tid] = acc;
        }
        __syncthreads();
        if (tid < 128) {
            float acc = 0.f;
            const float4* kr = reinterpret_cast<const float4*>(k2 + tid * 128);
            #pragma unroll 8
            for (int d4 = 0; d4 < 32; d4++) {
                float4 kv = kr[d4];
                float4 vv = *reinterpret_cast<const float4*>(&V1[d4 * 4]);
                acc += kv.x * vv.x + kv.y * vv.y + kv.z * vv.z + kv.w * vv.w;
            }
            V2[tid] = acc;
        }
        __syncthreads();
        #pragma unroll
        for (int r = 0; r < 8; r++) {
            int j = rowBase + r;
            float4 sv = *reinterpret_cast<const float4*>(&S[j * NPAD + lane * 4]);
            float4 vv = *reinterpret_cast<const float4*>(&V2[lane * 4]);
            float part = sv.x * vv.x + sv.y * vv.y + sv.z * vv.z + sv.w * vv.w;
            #pragma unroll
            for (int o = 16; o > 0; o >>= 1) part += __shfl_xor_sync(0xffffffffu, part, o);
            if (lane == 0)
                BR[j] = (MS[j] == 0.f) ? __int_as_float(0xff800000) : part * RSQ;
        }
        __syncthreads();
        if (warp == 0) {
            float l0 = BR[lane], l1 = BR[lane + 32];
            float m = fmaxf(l0, l1);
            #pragma unroll
            for (int o = 16; o > 0; o >>= 1) m = fmaxf(m, __shfl_xor_sync(0xffffffffu, m, o));
            float e0 = __expf(l0 - m);
            float e1 = __expf(l1 - m);
            float sE = e0 + e1;
            #pragma unroll
            for (int o = 16; o > 0; o >>= 1) sE += __shfl_xor_sync(0xffffffffu, sE, o);
            float inv = 1.f / sE;
            BR[lane]      = e0 * inv;
            BR[lane + 32] = e1 * inv;
        }
        __syncthreads();
        if (tid < 128) {
            float acc = 0.f;
            #pragma unroll 8
            for (int j = 0; j < 64; j++) acc += BR[j] * S[j * NPAD + tid];
            STAR[tid] = acc;
        }
        __syncthreads();
    }

    // ================= gate =================
    // reload hidden into T (freed)
    for (int idx = tid; idx < NN * DD / 4; idx += 256) {
        int i  = idx >> 5;
        int c4 = (idx & 31) << 2;
        *reinterpret_cast<float4*>(&T[i * NPAD + c4]) = reinterpret_cast<const float4*>(hg)[idx];
    }
    float av[8][4];
    #pragma unroll
    for (int r = 0; r < 8; r++)
        for (int q = 0; q < 4; q++) av[r][q] = 0.f;

    for (int cch = 0; cch < 8; cch++) {
        const int c0 = cch * 32;
        __syncthreads();
        // stage W[do][c0..c0+31] transposed into P as [cc][do]
        for (int idx = tid; idx < 4096; idx += 256) {
            int doo = idx >> 5;
            int cc  = idx & 31;
            P[cc * NPAD + doo] = wlin[doo * 256 + c0 + cc];
        }
        __syncthreads();
        const float* SRC = (c0 < 128) ? T : S;
        const int cb = (c0 < 128) ? c0 : (c0 - 128);
        #pragma unroll
        for (int cc = 0; cc < 32; cc++) {
            float4 wv = *reinterpret_cast<const float4*>(&P[cc * NPAD + lane * 4]);
            #pragma unroll
            for (int r = 0; r < 8; r++) {
                float cv = SRC[(rowBase + r) * NPAD + cb + cc];
                av[r][0] += cv * wv.x;
                av[r][1] += cv * wv.y;
                av[r][2] += cv * wv.z;
                av[r][3] += cv * wv.w;
            }
        }
    }
    __syncthreads();

    float* ob = outp + (size_t)b * (NN * DD);
    #pragma unroll
    for (int r = 0; r < 8; r++) {
        int i = rowBase + r;
        float4 hv = *reinterpret_cast<const float4*>(&T[i * NPAD + lane * 4]);
        float4 sv = *reinterpret_cast<const float4*>(&S[i * NPAD + lane * 4]);
        float g0 = 1.f / (1.f + __expf(-av[r][0]));
        float g1 = 1.f / (1.f + __expf(-av[r][1]));
        float g2 = 1.f / (1.f + __expf(-av[r][2]));
        float g3 = 1.f / (1.f + __expf(-av[r][3]));
        float4 res;
        res.x = g0 * hv.x + (1.f - g0) * sv.x;
        res.y = g1 * hv.y + (1.f - g1) * sv.y;
        res.z = g2 * hv.z + (1.f - g2) * sv.z;
        res.w = g3 * hv.w + (1.f - g3) * sv.w;
        *reinterpret_cast<float4*>(&ob[i * 128 + lane * 4]) = res;
    }
    if (tid < 128) starp[(size_t)b * 128 + tid] = STAR[tid];
}

extern "C" void kernel_launch(void* const* d_in, const int* in_sizes, int n_in,
                              void* d_out, int out_size) {
    const float* hidden = (const float*)d_in[0];
    const int*   adj    = (const int*)d_in[1];
    const float* mask   = (const float*)d_in[2];
    const float* a0     = (const float*)d_in[3];
    const float* a1     = (const float*)d_in[4];
    const float* a2     = (const float*)d_in[5];
    const float* a3     = (const float*)d_in[6];
    const float* q1     = (const float*)d_in[7];
    const float* k1     = (const float*)d_in[8];
    const float* q2     = (const float*)d_in[9];
    const float* k2     = (const float*)d_in[10];
    const float* wlin   = (const float*)d_in[11];

    float* outp  = (float*)d_out;
    float* starp = outp + (size_t)NB * NN * DD;

    // smem: S+T (2*64*132) + P (4*64*36) + A(512) + STAR/V1/V2(384) + MS/BR(128) floats + ADJ(4096B)
    const size_t smem = (size_t)(2 * NN * NPAD + 4 * 64 * PCH + 512 + 384 + 128) * sizeof(float) + 4096;
    cudaFuncSetAttribute(star_agg_kernel, cudaFuncAttributeMaxDynamicSharedMemorySize, (int)smem);
    star_agg_kernel<<<NB, 256, smem>>>(hidden, adj, mask, a0, a1, a2, a3,
                                       q1, k1, q2, k2, wlin, outp, starp);
}

// round 2
// speedup vs baseline: 1.0219x; 1.0219x over previous
#include <cuda_runtime.h>

#define NB   2048
#define NN   64
#define DD   128
#define NPAD 132
#define NEG_BIG (-9000000000000000.0f)

// shared float offsets
#define OFF_S    0
#define OFF_U    8448            // union: P (8192) / T (8448) / PW (4608)
#define OFF_A    16896           // 4*128
#define OFF_STAR 17408
#define OFF_V1   17536
#define OFF_V2   17664
#define OFF_MS   17792
#define OFF_BR   17856
#define SM_FLOATS 17920
#define SM_BYTES  (SM_FLOATS * 4 + 4096)   // + ADJ bytes

__global__ void __launch_bounds__(256, 3)
star_agg_kernel(const float* __restrict__ hidden,
                const int*   __restrict__ adj,
                const float* __restrict__ mask,
                const float* __restrict__ a0,
                const float* __restrict__ a1,
                const float* __restrict__ a2,
                const float* __restrict__ a3,
                const float* __restrict__ q1,
                const float* __restrict__ k1,
                const float* __restrict__ q2,
                const float* __restrict__ k2,
                const float* __restrict__ wlin,
                float* __restrict__ outp,
                float* __restrict__ starp)
{
    extern __shared__ float sm[];
    float* S    = sm + OFF_S;
    float* U    = sm + OFF_U;     // P during e-dot, T after att@S, PW during gate
    float* A    = sm + OFF_A;
    float* STAR = sm + OFF_STAR;
    float* V1   = sm + OFF_V1;
    float* V2   = sm + OFF_V2;
    float* MS   = sm + OFF_MS;
    float* BR   = sm + OFF_BR;
    unsigned char* ADJ = (unsigned char*)(sm + SM_FLOATS);

    const int tid  = threadIdx.x;
    const int lane = tid & 31;
    const int warp = tid >> 5;
    const int b    = blockIdx.x;
    const int rowBase = warp * 8;

    const float* hg = hidden + (size_t)b * (NN * DD);
    const int*   ag = adj    + (size_t)b * (NN * NN);

    // ---- load hidden -> S, adj, a_k, mask ----
    for (int idx = tid; idx < NN * DD / 4; idx += 256) {
        int i  = idx >> 5;
        int c4 = (idx & 31) << 2;
        float4 v = reinterpret_cast<const float4*>(hg)[idx];
        *reinterpret_cast<float4*>(&S[i * NPAD + c4]) = v;
    }
    for (int idx = tid; idx < NN * NN; idx += 256)
        ADJ[idx] = (unsigned char)ag[idx];
    if (tid < 128) {
        A[tid]       = a0[tid];
        A[128 + tid] = a1[tid];
        A[256 + tid] = a2[tid];
        A[384 + tid] = a3[tid];
    }
    if (tid < 64) MS[tid] = mask[b * NN + tid];
    __syncthreads();

    // ---- star = masked mean ----
    if (tid < 128) {
        float acc = 0.f, msum = 0.f;
        #pragma unroll 8
        for (int i = 0; i < NN; i++) {
            acc  += S[i * NPAD + tid] * MS[i];
            msum += MS[i];
        }
        STAR[tid] = acc / msum;
    }
    __syncthreads();

    const float RSQ = 0.088388347648318447f;  // 1/sqrt(128)

    for (int step = 0; step < 2; step++) {
        // ================= local_agg: e-dots =================
        float acc0[8], acc1[8];
        int   base0[8], base1[8];
        #pragma unroll
        for (int r = 0; r < 8; r++) {
            acc0[r] = 0.f; acc1[r] = 0.f;
            int ka = ADJ[(rowBase + r) * 64 + lane];
            int kb = ADJ[(rowBase + r) * 64 + lane + 32];
            int sa = (ka == 0) ? 0 : ka - 1;
            int sb = (kb == 0) ? 0 : kb - 1;
            // P layout: [k][dd4][j] of float4 -> index ((k*8+dd4)*64 + j)*4
            base0[r] = sa * 2048 + (lane << 2);
            base1[r] = sb * 2048 + ((lane + 32) << 2);
        }
        for (int ch = 0; ch < 4; ch++) {
            const int d0 = ch * 32;
            __syncthreads();
            // build P[k][dd4][j][c] = a_k[d0+dd4*4+c] * S[j][d0+dd4*4+c]
            for (int idx = tid; idx < 2048; idx += 256) {
                int j   = idx & 63;
                int dd4 = (idx >> 6) & 7;
                int k   = idx >> 9;
                float4 av4 = *reinterpret_cast<const float4*>(&A[k * 128 + d0 + dd4 * 4]);
                float4 sv4 = *reinterpret_cast<const float4*>(&S[j * NPAD + d0 + dd4 * 4]);
                float4 p;
                p.x = av4.x * sv4.x; p.y = av4.y * sv4.y;
                p.z = av4.z * sv4.z; p.w = av4.w * sv4.w;
                *reinterpret_cast<float4*>(&U[idx << 2]) = p;
            }
            __syncthreads();
            #pragma unroll
            for (int dd4 = 0; dd4 < 8; dd4++) {
                #pragma unroll
                for (int r = 0; r < 8; r++) {
                    float4 si = *reinterpret_cast<const float4*>(&S[(rowBase + r) * NPAD + d0 + dd4 * 4]);
                    float4 p0 = *reinterpret_cast<const float4*>(&U[base0[r] + dd4 * 256]);
                    float4 p1 = *reinterpret_cast<const float4*>(&U[base1[r] + dd4 * 256]);
                    acc0[r] += si.x * p0.x + si.y * p0.y + si.z * p0.z + si.w * p0.w;
                    acc1[r] += si.x * p1.x + si.y * p1.y + si.z * p1.z + si.w * p1.w;
                }
            }
        }
        // leaky + adj-mask + row softmax
        float att0[8], att1[8];
        #pragma unroll
        for (int r = 0; r < 8; r++) {
            int i = rowBase + r;
            int ka = ADJ[i * 64 + lane];
            int kb = ADJ[i * 64 + lane + 32];
            float dv0 = acc0[r], dv1 = acc1[r];
            float l0 = (ka == 0) ? NEG_BIG : (dv0 >= 0.f ? dv0 : 0.2f * dv0);
            float l1 = (kb == 0) ? NEG_BIG : (dv1 >= 0.f ? dv1 : 0.2f * dv1);
            float m = fmaxf(l0, l1);
            #pragma unroll
            for (int o = 16; o > 0; o >>= 1) m = fmaxf(m, __shfl_xor_sync(0xffffffffu, m, o));
            float e0 = __expf(l0 - m);
            float e1 = __expf(l1 - m);
            float sE = e0 + e1;
            #pragma unroll
            for (int o = 16; o > 0; o >>= 1) sE += __shfl_xor_sync(0xffffffffu, sE, o);
            float inv = 1.f / sE;
            att0[r] = e0 * inv;
            att1[r] = e1 * inv;
        }
        __syncthreads();   // all P reads done before T (=U) writes

        // ---- T = att @ S : one 8-row group so each S[j] load feeds 8 accums ----
        {
            float4 o0={0,0,0,0},o1={0,0,0,0},o2={0,0,0,0},o3={0,0,0,0};
            float4 o4={0,0,0,0},o5={0,0,0,0},o6={0,0,0,0},o7={0,0,0,0};
            for (int j = 0; j < 32; j++) {
                float4 sj = *reinterpret_cast<const float4*>(&S[j * NPAD + lane * 4]);
                float w;
                w = __shfl_sync(0xffffffffu, att0[0], j); o0.x+=w*sj.x; o0.y+=w*sj.y; o0.z+=w*sj.z; o0.w+=w*sj.w;
                w = __shfl_sync(0xffffffffu, att0[1], j); o1.x+=w*sj.x; o1.y+=w*sj.y; o1.z+=w*sj.z; o1.w+=w*sj.w;
                w = __shfl_sync(0xffffffffu, att0[2], j); o2.x+=w*sj.x; o2.y+=w*sj.y; o2.z+=w*sj.z; o2.w+=w*sj.w;
                w = __shfl_sync(0xffffffffu, att0[3], j); o3.x+=w*sj.x; o3.y+=w*sj.y; o3.z+=w*sj.z; o3.w+=w*sj.w;
                w = __shfl_sync(0xffffffffu, att0[4], j); o4.x+=w*sj.x; o4.y+=w*sj.y; o4.z+=w*sj.z; o4.w+=w*sj.w;
                w = __shfl_sync(0xffffffffu, att0[5], j); o5.x+=w*sj.x; o5.y+=w*sj.y; o5.z+=w*sj.z; o5.w+=w*sj.w;
                w = __shfl_sync(0xffffffffu, att0[6], j); o6.x+=w*sj.x; o6.y+=w*sj.y; o6.z+=w*sj.z; o6.w+=w*sj.w;
                w = __shfl_sync(0xffffffffu, att0[7], j); o7.x+=w*sj.x; o7.y+=w*sj.y; o7.z+=w*sj.z; o7.w+=w*sj.w;
            }
            for (int j = 0; j < 32; j++) {
                float4 sj = *reinterpret_cast<const float4*>(&S[(j + 32) * NPAD + lane * 4]);
                float w;
                w = __shfl_sync(0xffffffffu, att1[0], j); o0.x+=w*sj.x; o0.y+=w*sj.y; o0.z+=w*sj.z; o0.w+=w*sj.w;
                w = __shfl_sync(0xffffffffu, att1[1], j); o1.x+=w*sj.x; o1.y+=w*sj.y; o1.z+=w*sj.z; o1.w+=w*sj.w;
                w = __shfl_sync(0xffffffffu, att1[2], j); o2.x+=w*sj.x; o2.y+=w*sj.y; o2.z+=w*sj.z; o2.w+=w*sj.w;
                w = __shfl_sync(0xffffffffu, att1[3], j); o3.x+=w*sj.x; o3.y+=w*sj.y; o3.z+=w*sj.z; o3.w+=w*sj.w;
                w = __shfl_sync(0xffffffffu, att1[4], j); o4.x+=w*sj.x; o4.y+=w*sj.y; o4.z+=w*sj.z; o4.w+=w*sj.w;
                w = __shfl_sync(0xffffffffu, att1[5], j); o5.x+=w*sj.x; o5.y+=w*sj.y; o5.z+=w*sj.z; o5.w+=w*sj.w;
                w = __shfl_sync(0xffffffffu, att1[6], j); o6.x+=w*sj.x; o6.y+=w*sj.y; o6.z+=w*sj.z; o6.w+=w*sj.w;
                w = __shfl_sync(0xffffffffu, att1[7], j); o7.x+=w*sj.x; o7.y+=w*sj.y; o7.z+=w*sj.z; o7.w+=w*sj.w;
            }
            float* T = U;
            *reinterpret_cast<float4*>(&T[(rowBase + 0) * NPAD + lane * 4]) = o0;
            *reinterpret_cast<float4*>(&T[(rowBase + 1) * NPAD + lane * 4]) = o1;
            *reinterpret_cast<float4*>(&T[(rowBase + 2) * NPAD + lane * 4]) = o2;
            *reinterpret_cast<float4*>(&T[(rowBase + 3) * NPAD + lane * 4]) = o3;
            *reinterpret_cast<float4*>(&T[(rowBase + 4) * NPAD + lane * 4]) = o4;
            *reinterpret_cast<float4*>(&T[(rowBase + 5) * NPAD + lane * 4]) = o5;
            *reinterpret_cast<float4*>(&T[(rowBase + 6) * NPAD + lane * 4]) = o6;
            *reinterpret_cast<float4*>(&T[(rowBase + 7) * NPAD + lane * 4]) = o7;
        }
        __syncthreads();

        // ================ alpha update ================
        if (tid < 128) {
            float acc = 0.f;
            #pragma unroll 8
            for (int c = 0; c < 128; c++) acc += STAR[c] * k1[c * 128 + tid];
            V1[tid] = acc;
        }
        __syncthreads();
        if (tid < 128) {
            float acc = 0.f;
            const float4* qr = reinterpret_cast<const float4*>(q1 + tid * 128);
            #pragma unroll 8
            for (int d4 = 0; d4 < 32; d4++) {
                float4 qv = qr[d4];
                float4 vv = *reinterpret_cast<const float4*>(&V1[d4 * 4]);
                acc += qv.x * vv.x + qv.y * vv.y + qv.z * vv.z + qv.w * vv.w;
            }
            V2[tid] = acc;
        }
        __syncthreads();
        {
            float* T = U;
            #pragma unroll
            for (int r = 0; r < 8; r++) {
                int i = rowBase + r;
                float4 tv = *reinterpret_cast<const float4*>(&T[i * NPAD + lane * 4]);
                float4 qv = *reinterpret_cast<const float4*>(&V2[lane * 4]);
                float part = tv.x * qv.x + tv.y * qv.y + tv.z * qv.z + tv.w * qv.w;
                #pragma unroll
                for (int o = 16; o > 0; o >>= 1) part += __shfl_xor_sync(0xffffffffu, part, o);
                float al = part * RSQ;
                float4 st = *reinterpret_cast<const float4*>(&STAR[lane * 4]);
                float4 ns;
                ns.x = (1.f - al) * tv.x + al * st.x;
                ns.y = (1.f - al) * tv.y + al * st.y;
                ns.z = (1.f - al) * tv.z + al * st.z;
                ns.w = (1.f - al) * tv.w + al * st.w;
                *reinterpret_cast<float4*>(&S[i * NPAD + lane * 4]) = ns;
            }
        }
        __syncthreads();

        // ================ beta update ================
        if (tid < 128) {
            float acc = 0.f;
            #pragma unroll 8
            for (int c = 0; c < 128; c++) acc += STAR[c] * q2[c * 128 + tid];
            V1[tid] = acc;
        }
        __syncthreads();
        if (tid < 128) {
            float acc = 0.f;
            const float4* kr = reinterpret_cast<const float4*>(k2 + tid * 128);
            #pragma unroll 8
            for (int d4 = 0; d4 < 32; d4++) {
                float4 kv = kr[d4];
                float4 vv = *reinterpret_cast<const float4*>(&V1[d4 * 4]);
                acc += kv.x * vv.x + kv.y * vv.y + kv.z * vv.z + kv.w * vv.w;
            }
            V2[tid] = acc;
        }
        __syncthreads();
        #pragma unroll
        for (int r = 0; r < 8; r++) {
            int j = rowBase + r;
            float4 sv = *reinterpret_cast<const float4*>(&S[j * NPAD + lane * 4]);
            float4 vv = *reinterpret_cast<const float4*>(&V2[lane * 4]);
            float part = sv.x * vv.x + sv.y * vv.y + sv.z * vv.z + sv.w * vv.w;
            #pragma unroll
            for (int o = 16; o > 0; o >>= 1) part += __shfl_xor_sync(0xffffffffu, part, o);
            if (lane == 0)
                BR[j] = (MS[j] == 0.f) ? __int_as_float(0xff800000) : part * RSQ;
        }
        __syncthreads();
        if (warp == 0) {
            float l0 = BR[lane], l1 = BR[lane + 32];
            float m = fmaxf(l0, l1);
            #pragma unroll
            for (int o = 16; o > 0; o >>= 1) m = fmaxf(m, __shfl_xor_sync(0xffffffffu, m, o));
            float e0 = __expf(l0 - m);
            float e1 = __expf(l1 - m);
            float sE = e0 + e1;
            #pragma unroll
            for (int o = 16; o > 0; o >>= 1) sE += __shfl_xor_sync(0xffffffffu, sE, o);
            float inv = 1.f / sE;
            BR[lane]      = e0 * inv;
            BR[lane + 32] = e1 * inv;
        }
        __syncthreads();
        if (tid < 128) {
            float acc = 0.f;
            #pragma unroll 8
            for (int j = 0; j < 64; j++) acc += BR[j] * S[j * NPAD + tid];
            STAR[tid] = acc;
        }
        __syncthreads();
    }

    // ================= gate =================
    // out[i][o] = sigmoid( sum_c cat(hidden,sate)[i][c] * W[o][c] ) blend
    // lane owns o = lane + 32*s ; W chunk staged in U as PW[o*36 + cc]
    float av[8][4];
    #pragma unroll
    for (int r = 0; r < 8; r++)
        #pragma unroll
        for (int q = 0; q < 4; q++) av[r][q] = 0.f;

    for (int cch = 0; cch < 8; cch++) {
        const int c0 = cch * 32;
        __syncthreads();
        for (int idx = tid; idx < 4096; idx += 256) {
            int doo = idx >> 5;
            int cc  = idx & 31;
            U[doo * 36 + cc] = wlin[doo * 256 + c0 + cc];
        }
        __syncthreads();
        const bool firstHalf = (c0 < 128);
        const int cb = firstHalf ? c0 : (c0 - 128);
        #pragma unroll
        for (int cc4 = 0; cc4 < 8; cc4++) {
            float4 cv[8];
            #pragma unroll
            for (int r = 0; r < 8; r++) {
                if (firstHalf)
                    cv[r] = __ldg(reinterpret_cast<const float4*>(&hg[(rowBase + r) * 128 + cb + cc4 * 4]));
                else
                    cv[r] = *reinterpret_cast<const float4*>(&S[(rowBase + r) * NPAD + cb + cc4 * 4]);
            }
            #pragma unroll
            for (int s = 0; s < 4; s++) {
                float4 w4 = *reinterpret_cast<const float4*>(&U[(lane + 32 * s) * 36 + cc4 * 4]);
                #pragma unroll
                for (int r = 0; r < 8; r++)
                    av[r][s] += cv[r].x * w4.x + cv[r].y * w4.y + cv[r].z * w4.z + cv[r].w * w4.w;
            }
        }
    }
    __syncthreads();

    float* ob = outp + (size_t)b * (NN * DD);
    #pragma unroll
    for (int r = 0; r < 8; r++) {
        int i = rowBase + r;
        #pragma unroll
        for (int s = 0; s < 4; s++) {
            int o = lane + 32 * s;
            float hvv = __ldg(&hg[i * 128 + o]);
            float svv = S[i * NPAD + o];
            float g = 1.f / (1.f + __expf(-av[r][s]));
            ob[i * 128 + o] = g * hvv + (1.f - g) * svv;
        }
    }
    if (tid < 128) starp[(size_t)b * 128 + tid] = STAR[tid];
}

extern "C" void kernel_launch(void* const* d_in, const int* in_sizes, int n_in,
                              void* d_out, int out_size) {
    const float* hidden = (const float*)d_in[0];
    const int*   adj    = (const int*)d_in[1];
    const float* mask   = (const float*)d_in[2];
    const float* a0     = (const float*)d_in[3];
    const float* a1     = (const float*)d_in[4];
    const float* a2     = (const float*)d_in[5];
    const float* a3     = (const float*)d_in[6];
    const float* q1     = (const float*)d_in[7];
    const float* k1     = (const float*)d_in[8];
    const float* q2     = (const float*)d_in[9];
    const float* k2     = (const float*)d_in[10];
    const float* wlin   = (const float*)d_in[11];

    float* outp  = (float*)d_out;
    float* starp = outp + (size_t)NB * NN * DD;

    cudaFuncSetAttribute(star_agg_kernel, cudaFuncAttributeMaxDynamicSharedMemorySize, SM_BYTES);
    star_agg_kernel<<<NB, 256, SM_BYTES>>>(hidden, adj, mask, a0, a1, a2, a3,
                                           q1, k1, q2, k2, wlin, outp, starp);
}

// round 3
// speedup vs baseline: 1.0224x; 1.0005x over previous
#include <cuda_runtime.h>

#define NB   2048
#define NN   64
#define DD   128
#define NPAD 132
#define NEG_BIG (-9000000000000000.0f)

// shared float offsets
#define OFF_S    0
#define OFF_U    8448            // union: P (8192) / T (8448) / PW (4608)
#define OFF_A    16896           // 4*128
#define OFF_STAR 17408
#define OFF_V1   17536
#define OFF_V2   17664
#define OFF_MS   17792
#define OFF_BR   17856
#define SM_FLOATS 17920
#define SM_BYTES  (SM_FLOATS * 4 + 4096)   // + ADJ bytes

__global__ void __launch_bounds__(256, 3)
star_agg_kernel(const float* __restrict__ hidden,
                const int*   __restrict__ adj,
                const float* __restrict__ mask,
                const float* __restrict__ a0,
                const float* __restrict__ a1,
                const float* __restrict__ a2,
                const float* __restrict__ a3,
                const float* __restrict__ q1,
                const float* __restrict__ k1,
                const float* __restrict__ q2,
                const float* __restrict__ k2,
                const float* __restrict__ wlin,
                float* __restrict__ outp,
                float* __restrict__ starp)
{
    extern __shared__ float sm[];
    float* S    = sm + OFF_S;
    float* U    = sm + OFF_U;     // P during e-dot, T after att@S, PW during gate
    float* A    = sm + OFF_A;
    float* STAR = sm + OFF_STAR;
    float* V1   = sm + OFF_V1;
    float* V2   = sm + OFF_V2;
    float* MS   = sm + OFF_MS;
    float* BR   = sm + OFF_BR;
    unsigned char* ADJ = (unsigned char*)(sm + SM_FLOATS);

    const int tid  = threadIdx.x;
    const int lane = tid & 31;
    const int warp = tid >> 5;
    const int b    = blockIdx.x;
    const int rowBase = warp * 8;

    const float* hg = hidden + (size_t)b * (NN * DD);
    const int*   ag = adj    + (size_t)b * (NN * NN);

    // ---- load hidden -> S, adj, a_k, mask ----
    for (int idx = tid; idx < NN * DD / 4; idx += 256) {
        int i  = idx >> 5;
        int c4 = (idx & 31) << 2;
        float4 v = reinterpret_cast<const float4*>(hg)[idx];
        *reinterpret_cast<float4*>(&S[i * NPAD + c4]) = v;
    }
    for (int idx = tid; idx < NN * NN; idx += 256)
        ADJ[idx] = (unsigned char)ag[idx];
    if (tid < 128) {
        A[tid]       = a0[tid];
        A[128 + tid] = a1[tid];
        A[256 + tid] = a2[tid];
        A[384 + tid] = a3[tid];
    }
    if (tid < 64) MS[tid] = mask[b * NN + tid];
    __syncthreads();

    // ---- star = masked mean ----
    if (tid < 128) {
        float acc = 0.f, msum = 0.f;
        #pragma unroll 8
        for (int i = 0; i < NN; i++) {
            acc  += S[i * NPAD + tid] * MS[i];
            msum += MS[i];
        }
        STAR[tid] = acc / msum;
    }
    __syncthreads();

    const float RSQ = 0.088388347648318447f;  // 1/sqrt(128)

    for (int step = 0; step < 2; step++) {
        // ================= local_agg: e-dots =================
        float acc0[8], acc1[8];
        int   base0[8], base1[8];
        #pragma unroll
        for (int r = 0; r < 8; r++) {
            acc0[r] = 0.f; acc1[r] = 0.f;
            int ka = ADJ[(rowBase + r) * 64 + lane];
            int kb = ADJ[(rowBase + r) * 64 + lane + 32];
            int sa = (ka == 0) ? 0 : ka - 1;
            int sb = (kb == 0) ? 0 : kb - 1;
            // P layout: [k][dd4][j] of float4 -> index ((k*8+dd4)*64 + j)*4
            base0[r] = sa * 2048 + (lane << 2);
            base1[r] = sb * 2048 + ((lane + 32) << 2);
        }
        for (int ch = 0; ch < 4; ch++) {
            const int d0 = ch * 32;
            __syncthreads();
            // build P[k][dd4][j][c] = a_k[d0+dd4*4+c] * S[j][d0+dd4*4+c]
            for (int idx = tid; idx < 2048; idx += 256) {
                int j   = idx & 63;
                int dd4 = (idx >> 6) & 7;
                int k   = idx >> 9;
                float4 av4 = *reinterpret_cast<const float4*>(&A[k * 128 + d0 + dd4 * 4]);
                float4 sv4 = *reinterpret_cast<const float4*>(&S[j * NPAD + d0 + dd4 * 4]);
                float4 p;
                p.x = av4.x * sv4.x; p.y = av4.y * sv4.y;
                p.z = av4.z * sv4.z; p.w = av4.w * sv4.w;
                *reinterpret_cast<float4*>(&U[idx << 2]) = p;
            }
            __syncthreads();
            #pragma unroll
            for (int dd4 = 0; dd4 < 8; dd4++) {
                #pragma unroll
                for (int r = 0; r < 8; r++) {
                    float4 si = *reinterpret_cast<const float4*>(&S[(rowBase + r) * NPAD + d0 + dd4 * 4]);
                    float4 p0 = *reinterpret_cast<const float4*>(&U[base0[r] + dd4 * 256]);
                    float4 p1 = *reinterpret_cast<const float4*>(&U[base1[r] + dd4 * 256]);
                    acc0[r] += si.x * p0.x + si.y * p0.y + si.z * p0.z + si.w * p0.w;
                    acc1[r] += si.x * p1.x + si.y * p1.y + si.z * p1.z + si.w * p1.w;
                }
            }
        }
        // leaky + adj-mask + row softmax
        float att0[8], att1[8];
        #pragma unroll
        for (int r = 0; r < 8; r++) {
            int i = rowBase + r;
            int ka = ADJ[i * 64 + lane];
            int kb = ADJ[i * 64 + lane + 32];
            float dv0 = acc0[r], dv1 = acc1[r];
            float l0 = (ka == 0) ? NEG_BIG : (dv0 >= 0.f ? dv0 : 0.2f * dv0);
            float l1 = (kb == 0) ? NEG_BIG : (dv1 >= 0.f ? dv1 : 0.2f * dv1);
            float m = fmaxf(l0, l1);
            #pragma unroll
            for (int o = 16; o > 0; o >>= 1) m = fmaxf(m, __shfl_xor_sync(0xffffffffu, m, o));
            float e0 = __expf(l0 - m);
            float e1 = __expf(l1 - m);
            float sE = e0 + e1;
            #pragma unroll
            for (int o = 16; o > 0; o >>= 1) sE += __shfl_xor_sync(0xffffffffu, sE, o);
            float inv = 1.f / sE;
            att0[r] = e0 * inv;
            att1[r] = e1 * inv;
        }
        __syncthreads();   // all P reads done before T (=U) writes

        // ---- T = att @ S : one 8-row group so each S[j] load feeds 8 accums ----
        {
            float4 o0={0,0,0,0},o1={0,0,0,0},o2={0,0,0,0},o3={0,0,0,0};
            float4 o4={0,0,0,0},o5={0,0,0,0},o6={0,0,0,0},o7={0,0,0,0};
            for (int j = 0; j < 32; j++) {
                float4 sj = *reinterpret_cast<const float4*>(&S[j * NPAD + lane * 4]);
                float w;
                w = __shfl_sync(0xffffffffu, att0[0], j); o0.x+=w*sj.x; o0.y+=w*sj.y; o0.z+=w*sj.z; o0.w+=w*sj.w;
                w = __shfl_sync(0xffffffffu, att0[1], j); o1.x+=w*sj.x; o1.y+=w*sj.y; o1.z+=w*sj.z; o1.w+=w*sj.w;
                w = __shfl_sync(0xffffffffu, att0[2], j); o2.x+=w*sj.x; o2.y+=w*sj.y; o2.z+=w*sj.z; o2.w+=w*sj.w;
                w = __shfl_sync(0xffffffffu, att0[3], j); o3.x+=w*sj.x; o3.y+=w*sj.y; o3.z+=w*sj.z; o3.w+=w*sj.w;
                w = __shfl_sync(0xffffffffu, att0[4], j); o4.x+=w*sj.x; o4.y+=w*sj.y; o4.z+=w*sj.z; o4.w+=w*sj.w;
                w = __shfl_sync(0xffffffffu, att0[5], j); o5.x+=w*sj.x; o5.y+=w*sj.y; o5.z+=w*sj.z; o5.w+=w*sj.w;
                w = __shfl_sync(0xffffffffu, att0[6], j); o6.x+=w*sj.x; o6.y+=w*sj.y; o6.z+=w*sj.z; o6.w+=w*sj.w;
                w = __shfl_sync(0xffffffffu, att0[7], j); o7.x+=w*sj.x; o7.y+=w*sj.y; o7.z+=w*sj.z; o7.w+=w*sj.w;
            }
            for (int j = 0; j < 32; j++) {
                float4 sj = *reinterpret_cast<const float4*>(&S[(j + 32) * NPAD + lane * 4]);
                float w;
                w = __shfl_sync(0xffffffffu, att1[0], j); o0.x+=w*sj.x; o0.y+=w*sj.y; o0.z+=w*sj.z; o0.w+=w*sj.w;
                w = __shfl_sync(0xffffffffu, att1[1], j); o1.x+=w*sj.x; o1.y+=w*sj.y; o1.z+=w*sj.z; o1.w+=w*sj.w;
                w = __shfl_sync(0xffffffffu, att1[2], j); o2.x+=w*sj.x; o2.y+=w*sj.y; o2.z+=w*sj.z; o2.w+=w*sj.w;
                w = __shfl_sync(0xffffffffu, att1[3], j); o3.x+=w*sj.x; o3.y+=w*sj.y; o3.z+=w*sj.z; o3.w+=w*sj.w;
                w = __shfl_sync(0xffffffffu, att1[4], j); o4.x+=w*sj.x; o4.y+=w*sj.y; o4.z+=w*sj.z; o4.w+=w*sj.w;
                w = __shfl_sync(0xffffffffu, att1[5], j); o5.x+=w*sj.x; o5.y+=w*sj.y; o5.z+=w*sj.z; o5.w+=w*sj.w;
                w = __shfl_sync(0xffffffffu, att1[6], j); o6.x+=w*sj.x; o6.y+=w*sj.y; o6.z+=w*sj.z; o6.w+=w*sj.w;
                w = __shfl_sync(0xffffffffu, att1[7], j); o7.x+=w*sj.x; o7.y+=w*sj.y; o7.z+=w*sj.z; o7.w+=w*sj.w;
            }
            float* T = U;
            *reinterpret_cast<float4*>(&T[(rowBase + 0) * NPAD + lane * 4]) = o0;
            *reinterpret_cast<float4*>(&T[(rowBase + 1) * NPAD + lane * 4]) = o1;
            *reinterpret_cast<float4*>(&T[(rowBase + 2) * NPAD + lane * 4]) = o2;
            *reinterpret_cast<float4*>(&T[(rowBase + 3) * NPAD + lane * 4]) = o3;
            *reinterpret_cast<float4*>(&T[(rowBase + 4) * NPAD + lane * 4]) = o4;
            *reinterpret_cast<float4*>(&T[(rowBase + 5) * NPAD + lane * 4]) = o5;
            *reinterpret_cast<float4*>(&T[(rowBase + 6) * NPAD + lane * 4]) = o6;
            *reinterpret_cast<float4*>(&T[(rowBase + 7) * NPAD + lane * 4]) = o7;
        }
        __syncthreads();

        // ================ alpha update ================
        if (tid < 128) {
            float acc = 0.f;
            #pragma unroll 8
            for (int c = 0; c < 128; c++) acc += STAR[c] * k1[c * 128 + tid];
            V1[tid] = acc;
        }
        __syncthreads();
        if (tid < 128) {
            float acc = 0.f;
            const float4* qr = reinterpret_cast<const float4*>(q1 + tid * 128);
            #pragma unroll 8
            for (int d4 = 0; d4 < 32; d4++) {
                float4 qv = qr[d4];
                float4 vv = *reinterpret_cast<const float4*>(&V1[d4 * 4]);
                acc += qv.x * vv.x + qv.y * vv.y + qv.z * vv.z + qv.w * vv.w;
            }
            V2[tid] = acc;
        }
        __syncthreads();
        {
            float* T = U;
            #pragma unroll
            for (int r = 0; r < 8; r++) {
                int i = rowBase + r;
                float4 tv = *reinterpret_cast<const float4*>(&T[i * NPAD + lane * 4]);
                float4 qv = *reinterpret_cast<const float4*>(&V2[lane * 4]);
                float part = tv.x * qv.x + tv.y * qv.y + tv.z * qv.z + tv.w * qv.w;
                #pragma unroll
                for (int o = 16; o > 0; o >>= 1) part += __shfl_xor_sync(0xffffffffu, part, o);
                float al = part * RSQ;
                float4 st = *reinterpret_cast<const float4*>(&STAR[lane * 4]);
                float4 ns;
                ns.x = (1.f - al) * tv.x + al * st.x;
                ns.y = (1.f - al) * tv.y + al * st.y;
                ns.z = (1.f - al) * tv.z + al * st.z;
                ns.w = (1.f - al) * tv.w + al * st.w;
                *reinterpret_cast<float4*>(&S[i * NPAD + lane * 4]) = ns;
            }
        }
        __syncthreads();

        // ================ beta update ================
        if (tid < 128) {
            float acc = 0.f;
            #pragma unroll 8
            for (int c = 0; c < 128; c++) acc += STAR[c] * q2[c * 128 + tid];
            V1[tid] = acc;
        }
        __syncthreads();
        if (tid < 128) {
            float acc = 0.f;
            const float4* kr = reinterpret_cast<const float4*>(k2 + tid * 128);
            #pragma unroll 8
            for (int d4 = 0; d4 < 32; d4++) {
                float4 kv = kr[d4];
                float4 vv = *reinterpret_cast<const float4*>(&V1[d4 * 4]);
                acc += kv.x * vv.x + kv.y * vv.y + kv.z * vv.z + kv.w * vv.w;
            }
            V2[tid] = acc;
        }
        __syncthreads();
        #pragma unroll
        for (int r = 0; r < 8; r++) {
            int j = rowBase + r;
            float4 sv = *reinterpret_cast<const float4*>(&S[j * NPAD + lane * 4]);
            float4 vv = *reinterpret_cast<const float4*>(&V2[lane * 4]);
            float part = sv.x * vv.x + sv.y * vv.y + sv.z * vv.z + sv.w * vv.w;
            #pragma unroll
            for (int o = 16; o > 0; o >>= 1) part += __shfl_xor_sync(0xffffffffu, part, o);
            if (lane == 0)
                BR[j] = (MS[j] == 0.f) ? __int_as_float(0xff800000) : part * RSQ;
        }
        __syncthreads();
        if (warp == 0) {
            float l0 = BR[lane], l1 = BR[lane + 32];
            float m = fmaxf(l0, l1);
            #pragma unroll
            for (int o = 16; o > 0; o >>= 1) m = fmaxf(m, __shfl_xor_sync(0xffffffffu, m, o));
            float e0 = __expf(l0 - m);
            float e1 = __expf(l1 - m);
            float sE = e0 + e1;
            #pragma unroll
            for (int o = 16; o > 0; o >>= 1) sE += __shfl_xor_sync(0xffffffffu, sE, o);
            float inv = 1.f / sE;
            BR[lane]      = e0 * inv;
            BR[lane + 32] = e1 * inv;
        }
        __syncthreads();
        if (tid < 128) {
            float acc = 0.f;
            #pragma unroll 8
            for (int j = 0; j < 64; j++) acc += BR[j] * S[j * NPAD + tid];
            STAR[tid] = acc;
        }
        __syncthreads();
    }

    // ================= gate =================
    // out[i][o] = sigmoid( sum_c cat(hidden,sate)[i][c] * W[o][c] ) blend
    // lane owns o = lane + 32*s ; W chunk staged in U as PW[o*36 + cc]
    float av[8][4];
    #pragma unroll
    for (int r = 0; r < 8; r++)
        #pragma unroll
        for (int q = 0; q < 4; q++) av[r][q] = 0.f;

    for (int cch = 0; cch < 8; cch++) {
        const int c0 = cch * 32;
        __syncthreads();
        for (int idx = tid; idx < 4096; idx += 256) {
            int doo = idx >> 5;
            int cc  = idx & 31;
            U[doo * 36 + cc] = wlin[doo * 256 + c0 + cc];
        }
        __syncthreads();
        const bool firstHalf = (c0 < 128);
        const int cb = firstHalf ? c0 : (c0 - 128);
        #pragma unroll
        for (int cc4 = 0; cc4 < 8; cc4++) {
            float4 cv[8];
            #pragma unroll
            for (int r = 0; r < 8; r++) {
                if (firstHalf)
                    cv[r] = __ldg(reinterpret_cast<const float4*>(&hg[(rowBase + r) * 128 + cb + cc4 * 4]));
                else
                    cv[r] = *reinterpret_cast<const float4*>(&S[(rowBase + r) * NPAD + cb + cc4 * 4]);
            }
            #pragma unroll
            for (int s = 0; s < 4; s++) {
                float4 w4 = *reinterpret_cast<const float4*>(&U[(lane + 32 * s) * 36 + cc4 * 4]);
                #pragma unroll
                for (int r = 0; r < 8; r++)
                    av[r][s] += cv[r].x * w4.x + cv[r].y * w4.y + cv[r].z * w4.z + cv[r].w * w4.w;
            }
        }
    }
    __syncthreads();

    float* ob = outp + (size_t)b * (NN * DD);
    #pragma unroll
    for (int r = 0; r < 8; r++) {
        int i = rowBase + r;
        #pragma unroll
        for (int s = 0; s < 4; s++) {
            int o = lane + 32 * s;
            float hvv = __ldg(&hg[i * 128 + o]);
            float svv = S[i * NPAD + o];
            float g = 1.f / (1.f + __expf(-av[r][s]));
            ob[i * 128 + o] = g * hvv + (1.f - g) * svv;
        }
    }
    if (tid < 128) starp[(size_t)b * 128 + tid] = STAR[tid];
}

extern "C" void kernel_launch(void* const* d_in, const int* in_sizes, int n_in,
                              void* d_out, int out_size) {
    const float* hidden = (const float*)d_in[0];
    const int*   adj    = (const int*)d_in[1];
    const float* mask   = (const float*)d_in[2];
    const float* a0     = (const float*)d_in[3];
    const float* a1     = (const float*)d_in[4];
    const float* a2     = (const float*)d_in[5];
    const float* a3     = (const float*)d_in[6];
    const float* q1     = (const float*)d_in[7];
    const float* k1     = (const float*)d_in[8];
    const float* q2     = (const float*)d_in[9];
    const float* k2     = (const float*)d_in[10];
    const float* wlin   = (const float*)d_in[11];

    float* outp  = (float*)d_out;
    float* starp = outp + (size_t)NB * NN * DD;

    cudaFuncSetAttribute(star_agg_kernel, cudaFuncAttributeMaxDynamicSharedMemorySize, SM_BYTES);
    star_agg_kernel<<<NB, 256, SM_BYTES>>>(hidden, adj, mask, a0, a1, a2, a3,
                                           q1, k1, q2, k2, wlin, outp, starp);
}

// round 5
// speedup vs baseline: 1.1728x; 1.1472x over previous
#include <cuda_runtime.h>
#include <cuda_bf16.h>
#include <cstdint>

#define NB   2048
#define NN   64
#define NPAD 132
#define LP   65
#define NEG_BIG (-9000000000000000.0f)

// smem float offsets
#define OFF_S    0          // 64*132 fp32 sate
#define OFF_TILE 8448       // 8704 fl = 34816 B : bf16 hi/lo tile (X or Y_k) | T | gate W
#define OFF_L    17152      // 64*65 logits
#define OFF_A    21312      // 4*128 a_k
#define OFF_STAR 21824
#define OFF_V1   21952
#define OFF_V2   22080
#define OFF_MS   22208
#define OFF_BR   22272
#define SM_FLOATS 22336
#define SM_BYTES (SM_FLOATS*4 + 64*68)   // + adj bytes = 93696

#define TSTRIDE_B 272        // 136 bf16 per row
#define TILE_HALF 17408      // bytes: hi tile size (lo at +17408)

__device__ __forceinline__ uint32_t smem_u32(const void* p) {
    uint32_t a;
    asm("{ .reg .u64 t; cvta.to.shared.u64 t, %1; cvt.u32.u64 %0, t; }" : "=r"(a) : "l"(p));
    return a;
}
__device__ __forceinline__ uint32_t pack_bf2(__nv_bfloat16 a, __nv_bfloat16 b) {
    __nv_bfloat162 v = __halves2bfloat162(a, b);
    return *reinterpret_cast<uint32_t*>(&v);
}

#define LDSM4(r, addr) \
    asm volatile("ldmatrix.sync.aligned.m8n8.x4.shared.b16 {%0,%1,%2,%3}, [%4];" \
        : "=r"((r)[0]), "=r"((r)[1]), "=r"((r)[2]), "=r"((r)[3]) : "r"(addr))
#define LDSM2(r0, r1, addr) \
    asm volatile("ldmatrix.sync.aligned.m8n8.x2.shared.b16 {%0,%1}, [%2];" \
        : "=r"(r0), "=r"(r1) : "r"(addr))
#define MMA16816(c0,c1,c2,c3, a, b0,b1) \
    asm volatile("mma.sync.aligned.m16n8k16.row.col.f32.bf16.bf16.f32 " \
        "{%0,%1,%2,%3}, {%4,%5,%6,%7}, {%8,%9}, {%0,%1,%2,%3};" \
        : "+f"(c0), "+f"(c1), "+f"(c2), "+f"(c3) \
        : "r"((a)[0]), "r"((a)[1]), "r"((a)[2]), "r"((a)[3]), "r"(b0), "r"(b1))

// build 64x128 bf16 hi/lo tile (pad-136 rows) from S, optionally scaled by vec
__device__ __forceinline__ void build_tile(const float* S, const float* vec,
                                           char* tile, int tid) {
    for (int p = tid; p < 4096; p += 256) {
        int row = p >> 6;
        int d = (p & 63) << 1;
        float2 sv = *reinterpret_cast<const float2*>(&S[row * NPAD + d]);
        float x0 = sv.x, x1 = sv.y;
        if (vec) { x0 *= vec[d]; x1 *= vec[d + 1]; }
        __nv_bfloat16 h0 = __float2bfloat16_rn(x0), h1 = __float2bfloat16_rn(x1);
        __nv_bfloat16 g0 = __float2bfloat16_rn(x0 - __bfloat162float(h0));
        __nv_bfloat16 g1 = __float2bfloat16_rn(x1 - __bfloat162float(h1));
        int off = row * TSTRIDE_B + d * 2;
        *reinterpret_cast<uint32_t*>(tile + off)             = pack_bf2(h0, h1);
        *reinterpret_cast<uint32_t*>(tile + TILE_HALF + off) = pack_bf2(g0, g1);
    }
}

__global__ void __launch_bounds__(256, 2)
star_agg_kernel(const float* __restrict__ hidden, const int* __restrict__ adj,
                const float* __restrict__ mask,
                const float* __restrict__ a0, const float* __restrict__ a1,
                const float* __restrict__ a2, const float* __restrict__ a3,
                const float* __restrict__ q1, const float* __restrict__ k1,
                const float* __restrict__ q2, const float* __restrict__ k2,
                const float* __restrict__ wlin,
                float* __restrict__ outp, float* __restrict__ starp)
{
    extern __shared__ float sm[];
    float* S    = sm + OFF_S;
    float* T    = sm + OFF_TILE;    // aliases tile after MMAs done
    float* L    = sm + OFF_L;
    float* A    = sm + OFF_A;
    float* STAR = sm + OFF_STAR;
    float* V1   = sm + OFF_V1;
    float* V2   = sm + OFF_V2;
    float* MS   = sm + OFF_MS;
    float* BR   = sm + OFF_BR;
    char*  TILE = (char*)(sm + OFF_TILE);
    unsigned char* ADJ = (unsigned char*)(sm + SM_FLOATS);  // [i][j] stride 68

    const int tid  = threadIdx.x;
    const int lane = tid & 31;
    const int warp = tid >> 5;
    const int b    = blockIdx.x;
    const int rowBase = warp * 8;

    const uint32_t smb   = smem_u32(sm);
    const uint32_t TILEH = smb + OFF_TILE * 4;
    const float* hg = hidden + (size_t)b * (NN * 128);
    const int*   ag = adj    + (size_t)b * (NN * NN);

    for (int idx = tid; idx < NN * 128 / 4; idx += 256) {
        int i = idx >> 5, c4 = (idx & 31) << 2;
        *reinterpret_cast<float4*>(&S[i * NPAD + c4]) = reinterpret_cast<const float4*>(hg)[idx];
    }
    for (int idx = tid; idx < NN * NN; idx += 256)
        ADJ[(idx >> 6) * 68 + (idx & 63)] = (unsigned char)ag[idx];
    if (tid < 128) {
        A[tid] = a0[tid]; A[128 + tid] = a1[tid];
        A[256 + tid] = a2[tid]; A[384 + tid] = a3[tid];
    }
    if (tid < 64) MS[tid] = mask[b * NN + tid];
    __syncthreads();

    if (tid < 128) {
        float acc = 0.f, msum = 0.f;
        #pragma unroll 8
        for (int i = 0; i < NN; i++) { acc += S[i * NPAD + tid] * MS[i]; msum += MS[i]; }
        STAR[tid] = acc / msum;
    }
    __syncthreads();

    const float RSQ = 0.088388347648318447f;
    const int mstrip = warp & 3;
    const int nhalf  = warp >> 2;
    const int R0 = mstrip * 16;
    const int N0 = nhalf * 32;

    for (int step = 0; step < 2; step++) {
        // ===== build X = S (hi/lo) + pre-init L to NEG_BIG =====
        build_tile(S, nullptr, TILE, tid);
        for (int p = tid; p < NN * LP; p += 256) L[p] = NEG_BIG;
        __syncthreads();

        // ===== load A fragments (held in regs for the whole step) =====
        uint32_t ah[32], al[32];
        {
            int m4 = lane >> 3;
            uint32_t abase = TILEH + (uint32_t)(R0 + (lane & 7) + ((m4 & 1) << 3)) * TSTRIDE_B
                           + ((m4 >> 1) << 4);
            #pragma unroll
            for (int kt = 0; kt < 8; kt++) {
                LDSM4(&ah[kt * 4], abase + kt * 32);
                LDSM4(&al[kt * 4], abase + TILE_HALF + kt * 32);
            }
        }
        __syncthreads();

        // ===== per edge type: build Y_k, MMA, select =====
        const int lsel = lane & 15;
        const uint32_t bbase = TILEH + (uint32_t)(N0 + (lsel & 7)) * TSTRIDE_B
                             + ((lsel >> 3) << 4);
        for (int k = 0; k < 4; k++) {
            build_tile(S, A + k * 128, TILE, tid);
            __syncthreads();
            #pragma unroll
            for (int nt = 0; nt < 4; nt++) {
                float c0 = 0.f, c1 = 0.f, c2 = 0.f, c3 = 0.f;
                #pragma unroll
                for (int kt = 0; kt < 8; kt++) {
                    uint32_t bh0, bh1, bl0, bl1;
                    uint32_t ba = bbase + nt * (8 * TSTRIDE_B) + kt * 32;
                    LDSM2(bh0, bh1, ba);
                    LDSM2(bl0, bl1, ba + TILE_HALF);
                    MMA16816(c0, c1, c2, c3, &ah[kt * 4], bh0, bh1);
                    MMA16816(c0, c1, c2, c3, &ah[kt * 4], bl0, bl1);
                    MMA16816(c0, c1, c2, c3, &al[kt * 4], bh0, bh1);
                }
                // select into L where adj == k+1 (leaky applied)
                int i0 = R0 + (lane >> 2);
                int j0 = N0 + nt * 8 + ((lane & 3) << 1);
                int code = k + 1;
                if (ADJ[i0 * 68 + j0] == code)
                    L[i0 * LP + j0] = (c0 >= 0.f) ? c0 : 0.2f * c0;
                if (ADJ[i0 * 68 + j0 + 1] == code)
                    L[i0 * LP + j0 + 1] = (c1 >= 0.f) ? c1 : 0.2f * c1;
                if (ADJ[(i0 + 8) * 68 + j0] == code)
                    L[(i0 + 8) * LP + j0] = (c2 >= 0.f) ? c2 : 0.2f * c2;
                if (ADJ[(i0 + 8) * 68 + j0 + 1] == code)
                    L[(i0 + 8) * LP + j0 + 1] = (c3 >= 0.f) ? c3 : 0.2f * c3;
            }
            __syncthreads();
        }

        // ===== row softmax =====
        float att[2][8];
        #pragma unroll
        for (int r = 0; r < 8; r++) {
            int i = rowBase + r;
            float l0 = L[i * LP + lane], l1 = L[i * LP + lane + 32];
            float m = fmaxf(l0, l1);
            #pragma unroll
            for (int o = 16; o > 0; o >>= 1) m = fmaxf(m, __shfl_xor_sync(0xffffffffu, m, o));
            float e0 = __expf(l0 - m), e1 = __expf(l1 - m);
            float sE = e0 + e1;
            #pragma unroll
            for (int o = 16; o > 0; o >>= 1) sE += __shfl_xor_sync(0xffffffffu, sE, o);
            float inv = 1.f / sE;
            att[0][r] = e0 * inv; att[1][r] = e1 * inv;
        }

        // ===== T = att @ S  (T aliases TILE; Y dead) =====
        {
            float4 oo[8];
            #pragma unroll
            for (int r = 0; r < 8; r++) oo[r] = make_float4(0.f, 0.f, 0.f, 0.f);
            #pragma unroll
            for (int half = 0; half < 2; half++) {
                for (int j = 0; j < 32; j++) {
                    float4 sj = *reinterpret_cast<const float4*>(&S[(half * 32 + j) * NPAD + lane * 4]);
                    #pragma unroll
                    for (int r = 0; r < 8; r++) {
                        float w = __shfl_sync(0xffffffffu, att[half][r], j);
                        oo[r].x += w * sj.x; oo[r].y += w * sj.y;
                        oo[r].z += w * sj.z; oo[r].w += w * sj.w;
                    }
                }
            }
            #pragma unroll
            for (int r = 0; r < 8; r++)
                *reinterpret_cast<float4*>(&T[(rowBase + r) * NPAD + lane * 4]) = oo[r];
        }
        __syncthreads();

        // ===== alpha =====
        if (tid < 128) {
            float acc = 0.f;
            #pragma unroll 8
            for (int c = 0; c < 128; c++) acc += STAR[c] * k1[c * 128 + tid];
            V1[tid] = acc;
        }
        __syncthreads();
        if (tid < 128) {
            float acc = 0.f;
            const float4* qr = reinterpret_cast<const float4*>(q1 + tid * 128);
            #pragma unroll 8
            for (int d4 = 0; d4 < 32; d4++) {
                float4 qv = qr[d4];
                float4 vv = *reinterpret_cast<const float4*>(&V1[d4 * 4]);
                acc += qv.x * vv.x + qv.y * vv.y + qv.z * vv.z + qv.w * vv.w;
            }
            V2[tid] = acc;
        }
        __syncthreads();
        #pragma unroll
        for (int r = 0; r < 8; r++) {
            int i = rowBase + r;
            float4 tv = *reinterpret_cast<const float4*>(&T[i * NPAD + lane * 4]);
            float4 qv = *reinterpret_cast<const float4*>(&V2[lane * 4]);
            float part = tv.x * qv.x + tv.y * qv.y + tv.z * qv.z + tv.w * qv.w;
            #pragma unroll
            for (int o = 16; o > 0; o >>= 1) part += __shfl_xor_sync(0xffffffffu, part, o);
            float al2 = part * RSQ;
            float4 st = *reinterpret_cast<const float4*>(&STAR[lane * 4]);
            float4 ns;
            ns.x = (1.f - al2) * tv.x + al2 * st.x;
            ns.y = (1.f - al2) * tv.y + al2 * st.y;
            ns.z = (1.f - al2) * tv.z + al2 * st.z;
            ns.w = (1.f - al2) * tv.w + al2 * st.w;
            *reinterpret_cast<float4*>(&S[i * NPAD + lane * 4]) = ns;
        }
        __syncthreads();

        // ===== beta =====
        if (tid < 128) {
            float acc = 0.f;
            #pragma unroll 8
            for (int c = 0; c < 128; c++) acc += STAR[c] * q2[c * 128 + tid];
            V1[tid] = acc;
        }
        __syncthreads();
        if (tid < 128) {
            float acc = 0.f;
            const float4* kr = reinterpret_cast<const float4*>(k2 + tid * 128);
            #pragma unroll 8
            for (int d4 = 0; d4 < 32; d4++) {
                float4 kv = kr[d4];
                float4 vv = *reinterpret_cast<const float4*>(&V1[d4 * 4]);
                acc += kv.x * vv.x + kv.y * vv.y + kv.z * vv.z + kv.w * vv.w;
            }
            V2[tid] = acc;
        }
        __syncthreads();
        #pragma unroll
        for (int r = 0; r < 8; r++) {
            int j = rowBase + r;
            float4 sv = *reinterpret_cast<const float4*>(&S[j * NPAD + lane * 4]);
            float4 vv = *reinterpret_cast<const float4*>(&V2[lane * 4]);
            float part = sv.x * vv.x + sv.y * vv.y + sv.z * vv.z + sv.w * vv.w;
            #pragma unroll
            for (int o = 16; o > 0; o >>= 1) part += __shfl_xor_sync(0xffffffffu, part, o);
            if (lane == 0)
                BR[j] = (MS[j] == 0.f) ? __int_as_float(0xff800000) : part * RSQ;
        }
        __syncthreads();
        if (warp == 0) {
            float l0 = BR[lane], l1 = BR[lane + 32];
            float m = fmaxf(l0, l1);
            #pragma unroll
            for (int o = 16; o > 0; o >>= 1) m = fmaxf(m, __shfl_xor_sync(0xffffffffu, m, o));
            float e0 = __expf(l0 - m), e1 = __expf(l1 - m);
            float sE = e0 + e1;
            #pragma unroll
            for (int o = 16; o > 0; o >>= 1) sE += __shfl_xor_sync(0xffffffffu, sE, o);
            float inv = 1.f / sE;
            BR[lane] = e0 * inv; BR[lane + 32] = e1 * inv;
        }
        __syncthreads();
        if (tid < 128) {
            float acc = 0.f;
            #pragma unroll 8
            for (int j = 0; j < 64; j++) acc += BR[j] * S[j * NPAD + tid];
            STAR[tid] = acc;
        }
        __syncthreads();
    }

    // ===== gate (W staged in TILE region) =====
    float* U = sm + OFF_TILE;
    float av[8][4];
    #pragma unroll
    for (int r = 0; r < 8; r++)
        #pragma unroll
        for (int q = 0; q < 4; q++) av[r][q] = 0.f;

    for (int cch = 0; cch < 8; cch++) {
        const int c0 = cch * 32;
        __syncthreads();
        for (int idx = tid; idx < 4096; idx += 256)
            U[(idx >> 5) * 36 + (idx & 31)] = wlin[(idx >> 5) * 256 + c0 + (idx & 31)];
        __syncthreads();
        const bool firstHalf = (c0 < 128);
        const int cb = firstHalf ? c0 : (c0 - 128);
        #pragma unroll
        for (int cc4 = 0; cc4 < 8; cc4++) {
            float4 cv[8];
            #pragma unroll
            for (int r = 0; r < 8; r++) {
                if (firstHalf)
                    cv[r] = __ldg(reinterpret_cast<const float4*>(&hg[(rowBase + r) * 128 + cb + cc4 * 4]));
                else
                    cv[r] = *reinterpret_cast<const float4*>(&S[(rowBase + r) * NPAD + cb + cc4 * 4]);
            }
            #pragma unroll
            for (int s = 0; s < 4; s++) {
                float4 w4 = *reinterpret_cast<const float4*>(&U[(lane + 32 * s) * 36 + cc4 * 4]);
                #pragma unroll
                for (int r = 0; r < 8; r++)
                    av[r][s] += cv[r].x * w4.x + cv[r].y * w4.y + cv[r].z * w4.z + cv[r].w * w4.w;
            }
        }
    }
    __syncthreads();

    float* ob = outp + (size_t)b * (NN * 128);
    #pragma unroll
    for (int r = 0; r < 8; r++) {
        int i = rowBase + r;
        #pragma unroll
        for (int s = 0; s < 4; s++) {
            int o = lane + 32 * s;
            float g = 1.f / (1.f + __expf(-av[r][s]));
            ob[i * 128 + o] = g * __ldg(&hg[i * 128 + o]) + (1.f - g) * S[i * NPAD + o];
        }
    }
    if (tid < 128) starp[(size_t)b * 128 + tid] = STAR[tid];
}

extern "C" void kernel_launch(void* const* d_in, const int* in_sizes, int n_in,
                              void* d_out, int out_size) {
    float* outp  = (float*)d_out;
    float* starp = outp + (size_t)NB * NN * 128;

    cudaFuncSetAttribute(star_agg_kernel, cudaFuncAttributeMaxDynamicSharedMemorySize, SM_BYTES);
    star_agg_kernel<<<NB, 256, SM_BYTES>>>(
        (const float*)d_in[0], (const int*)d_in[1], (const float*)d_in[2],
        (const float*)d_in[3], (const float*)d_in[4], (const float*)d_in[5], (const float*)d_in[6],
        (const float*)d_in[7], (const float*)d_in[8], (const float*)d_in[9], (const float*)d_in[10],
        (const float*)d_in[11], outp, starp);
}

// round 6
// speedup vs baseline: 1.2551x; 1.0702x over previous
#include <cuda_runtime.h>
#include <cuda_bf16.h>
#include <cstdint>

#define NB   2048
#define NN   64
#define NPAD 132
#define LP   65
#define NEG_BIG (-9000000000000000.0f)

// smem float offsets
#define OFF_S    0          // 64*132 fp32 sate
#define OFF_TILE 8448       // 8704 fl = 34816 B : bf16 hi/lo tile | gate W
#define OFF_L    17152      // 64*65 logits
#define OFF_A    21312      // 4*128 a_k
#define OFF_STAR 21824
#define OFF_V1A  21952
#define OFF_V2A  22080
#define OFF_V1B  22208
#define OFF_V2B  22336
#define OFF_MS   22464
#define OFF_BR   22528
#define SM_FLOATS 22592
#define SM_BYTES (SM_FLOATS*4 + 64*68)

#define TSTRIDE_B 272        // 136 bf16 per row
#define TILE_HALF 17408      // bytes: hi tile size (lo at +17408)

__device__ __forceinline__ uint32_t smem_u32(const void* p) {
    uint32_t a;
    asm("{ .reg .u64 t; cvta.to.shared.u64 t, %1; cvt.u32.u64 %0, t; }" : "=r"(a) : "l"(p));
    return a;
}
__device__ __forceinline__ uint32_t pack_bf2(__nv_bfloat16 a, __nv_bfloat16 b) {
    __nv_bfloat162 v = __halves2bfloat162(a, b);
    return *reinterpret_cast<uint32_t*>(&v);
}

#define LDSM4(r, addr) \
    asm volatile("ldmatrix.sync.aligned.m8n8.x4.shared.b16 {%0,%1,%2,%3}, [%4];" \
        : "=r"((r)[0]), "=r"((r)[1]), "=r"((r)[2]), "=r"((r)[3]) : "r"(addr))
#define LDSM2(r0, r1, addr) \
    asm volatile("ldmatrix.sync.aligned.m8n8.x2.shared.b16 {%0,%1}, [%2];" \
        : "=r"(r0), "=r"(r1) : "r"(addr))
#define MMA16816(c0,c1,c2,c3, a, b0,b1) \
    asm volatile("mma.sync.aligned.m16n8k16.row.col.f32.bf16.bf16.f32 " \
        "{%0,%1,%2,%3}, {%4,%5,%6,%7}, {%8,%9}, {%0,%1,%2,%3};" \
        : "+f"(c0), "+f"(c1), "+f"(c2), "+f"(c3) \
        : "r"((a)[0]), "r"((a)[1]), "r"((a)[2]), "r"((a)[3]), "r"(b0), "r"(b1))

__device__ __forceinline__ void build_tile(const float* S, const float* vec,
                                           char* tile, int tid) {
    for (int p = tid; p < 4096; p += 256) {
        int row = p >> 6;
        int d = (p & 63) << 1;
        float2 sv = *reinterpret_cast<const float2*>(&S[row * NPAD + d]);
        float x0 = sv.x, x1 = sv.y;
        if (vec) { x0 *= vec[d]; x1 *= vec[d + 1]; }
        __nv_bfloat16 h0 = __float2bfloat16_rn(x0), h1 = __float2bfloat16_rn(x1);
        __nv_bfloat16 g0 = __float2bfloat16_rn(x0 - __bfloat162float(h0));
        __nv_bfloat16 g1 = __float2bfloat16_rn(x1 - __bfloat162float(h1));
        int off = row * TSTRIDE_B + d * 2;
        *reinterpret_cast<uint32_t*>(tile + off)             = pack_bf2(h0, h1);
        *reinterpret_cast<uint32_t*>(tile + TILE_HALF + off) = pack_bf2(g0, g1);
    }
}

__global__ void __launch_bounds__(256, 2)
star_agg_kernel(const float* __restrict__ hidden, const int* __restrict__ adj,
                const float* __restrict__ mask,
                const float* __restrict__ a0, const float* __restrict__ a1,
                const float* __restrict__ a2, const float* __restrict__ a3,
                const float* __restrict__ q1, const float* __restrict__ k1,
                const float* __restrict__ q2, const float* __restrict__ k2,
                const float* __restrict__ wlin,
                float* __restrict__ outp, float* __restrict__ starp)
{
    extern __shared__ float sm[];
    float* S    = sm + OFF_S;
    float* L    = sm + OFF_L;
    float* A    = sm + OFF_A;
    float* STAR = sm + OFF_STAR;
    float* V1A  = sm + OFF_V1A;
    float* V2A  = sm + OFF_V2A;
    float* V1B  = sm + OFF_V1B;
    float* V2B  = sm + OFF_V2B;
    float* MS   = sm + OFF_MS;
    float* BR   = sm + OFF_BR;
    char*  TILE = (char*)(sm + OFF_TILE);
    unsigned char* ADJ = (unsigned char*)(sm + SM_FLOATS);  // [i][j] stride 68

    const int tid  = threadIdx.x;
    const int lane = tid & 31;
    const int warp = tid >> 5;
    const int b    = blockIdx.x;
    const int rowBase = warp * 8;

    const uint32_t smb   = smem_u32(sm);
    const uint32_t TILEH = smb + OFF_TILE * 4;
    const float* hg = hidden + (size_t)b * (NN * 128);
    const int*   ag = adj    + (size_t)b * (NN * NN);

    for (int idx = tid; idx < NN * 128 / 4; idx += 256) {
        int i = idx >> 5, c4 = (idx & 31) << 2;
        *reinterpret_cast<float4*>(&S[i * NPAD + c4]) = reinterpret_cast<const float4*>(hg)[idx];
    }
    for (int idx = tid; idx < NN * NN; idx += 256)
        ADJ[(idx >> 6) * 68 + (idx & 63)] = (unsigned char)ag[idx];
    if (tid < 128) {
        A[tid] = a0[tid]; A[128 + tid] = a1[tid];
        A[256 + tid] = a2[tid]; A[384 + tid] = a3[tid];
    }
    if (tid < 64) MS[tid] = mask[b * NN + tid];
    __syncthreads();

    if (tid < 128) {
        float acc = 0.f, msum = 0.f;
        #pragma unroll 8
        for (int i = 0; i < NN; i++) { acc += S[i * NPAD + tid] * MS[i]; msum += MS[i]; }
        STAR[tid] = acc / msum;
    }
    __syncthreads();

    const float RSQ = 0.088388347648318447f;
    const int mstrip = warp & 3;
    const int nhalf  = warp >> 2;
    const int R0 = mstrip * 16;
    const int N0 = nhalf * 32;

    for (int step = 0; step < 2; step++) {
        // ===== alpha/beta mat-vecs (depend only on STAR) — both pairs in parallel =====
        {
            const int g = warp >> 2;           // 0: alpha pair, 1: beta pair
            const int t = tid & 127;
            const float* M1 = g ? q2 : k1;
            const float* M2 = g ? k2 : q1;
            float* V1g = g ? V1B : V1A;
            float* V2g = g ? V2B : V2A;
            float s0 = 0.f, s1 = 0.f, s2 = 0.f, s3 = 0.f;
            #pragma unroll 8
            for (int c = 0; c < 128; c += 4) {
                s0 += STAR[c]     * M1[c * 128 + t];
                s1 += STAR[c + 1] * M1[(c + 1) * 128 + t];
                s2 += STAR[c + 2] * M1[(c + 2) * 128 + t];
                s3 += STAR[c + 3] * M1[(c + 3) * 128 + t];
            }
            V1g[t] = (s0 + s1) + (s2 + s3);
            asm volatile("bar.sync %0, 128;" :: "r"(g + 1) : "memory");
            float acc = 0.f;
            const float4* mr = reinterpret_cast<const float4*>(M2 + t * 128);
            #pragma unroll 8
            for (int d4 = 0; d4 < 32; d4++) {
                float4 mv = mr[d4];
                float4 vv = *reinterpret_cast<const float4*>(&V1g[d4 * 4]);
                acc += mv.x * vv.x + mv.y * vv.y + mv.z * vv.z + mv.w * vv.w;
            }
            V2g[t] = acc;
        }

        // ===== build X = S (hi/lo) + init L =====
        build_tile(S, nullptr, TILE, tid);
        for (int p = tid; p < NN * LP; p += 256) L[p] = NEG_BIG;
        __syncthreads();

        // ===== A fragments (held in regs for the step) =====
        uint32_t ah[32], al[32];
        {
            int m4 = lane >> 3;
            uint32_t abase = TILEH + (uint32_t)(R0 + (lane & 7) + ((m4 & 1) << 3)) * TSTRIDE_B
                           + ((m4 >> 1) << 4);
            #pragma unroll
            for (int kt = 0; kt < 8; kt++) {
                LDSM4(&ah[kt * 4], abase + kt * 32);
                LDSM4(&al[kt * 4], abase + TILE_HALF + kt * 32);
            }
        }
        __syncthreads();

        // ===== per edge type: build Y_k, MMA, select =====
        const int lsel = lane & 15;
        const uint32_t bbase = TILEH + (uint32_t)(N0 + (lsel & 7)) * TSTRIDE_B
                             + ((lsel >> 3) << 4);
        for (int k = 0; k < 4; k++) {
            build_tile(S, A + k * 128, TILE, tid);
            __syncthreads();
            #pragma unroll
            for (int nt = 0; nt < 4; nt++) {
                float c0 = 0.f, c1 = 0.f, c2 = 0.f, c3 = 0.f;
                #pragma unroll
                for (int kt = 0; kt < 8; kt++) {
                    uint32_t bh0, bh1, bl0, bl1;
                    uint32_t ba = bbase + nt * (8 * TSTRIDE_B) + kt * 32;
                    LDSM2(bh0, bh1, ba);
                    LDSM2(bl0, bl1, ba + TILE_HALF);
                    MMA16816(c0, c1, c2, c3, &ah[kt * 4], bh0, bh1);
                    MMA16816(c0, c1, c2, c3, &ah[kt * 4], bl0, bl1);
                    MMA16816(c0, c1, c2, c3, &al[kt * 4], bh0, bh1);
                }
                int i0 = R0 + (lane >> 2);
                int j0 = N0 + nt * 8 + ((lane & 3) << 1);
                int code = k + 1;
                if (ADJ[i0 * 68 + j0] == code)
                    L[i0 * LP + j0] = (c0 >= 0.f) ? c0 : 0.2f * c0;
                if (ADJ[i0 * 68 + j0 + 1] == code)
                    L[i0 * LP + j0 + 1] = (c1 >= 0.f) ? c1 : 0.2f * c1;
                if (ADJ[(i0 + 8) * 68 + j0] == code)
                    L[(i0 + 8) * LP + j0] = (c2 >= 0.f) ? c2 : 0.2f * c2;
                if (ADJ[(i0 + 8) * 68 + j0 + 1] == code)
                    L[(i0 + 8) * LP + j0 + 1] = (c3 >= 0.f) ? c3 : 0.2f * c3;
            }
            __syncthreads();
        }

        // ===== row softmax =====
        float att[2][8];
        #pragma unroll
        for (int r = 0; r < 8; r++) {
            int i = rowBase + r;
            float l0 = L[i * LP + lane], l1 = L[i * LP + lane + 32];
            float m = fmaxf(l0, l1);
            #pragma unroll
            for (int o = 16; o > 0; o >>= 1) m = fmaxf(m, __shfl_xor_sync(0xffffffffu, m, o));
            float e0 = __expf(l0 - m), e1 = __expf(l1 - m);
            float sE = e0 + e1;
            #pragma unroll
            for (int o = 16; o > 0; o >>= 1) sE += __shfl_xor_sync(0xffffffffu, sE, o);
            float inv = 1.f / sE;
            att[0][r] = e0 * inv; att[1][r] = e1 * inv;
        }

        // ===== att @ S in registers =====
        float4 oo[8];
        #pragma unroll
        for (int r = 0; r < 8; r++) oo[r] = make_float4(0.f, 0.f, 0.f, 0.f);
        #pragma unroll
        for (int half = 0; half < 2; half++) {
            for (int j = 0; j < 32; j++) {
                float4 sj = *reinterpret_cast<const float4*>(&S[(half * 32 + j) * NPAD + lane * 4]);
                #pragma unroll
                for (int r = 0; r < 8; r++) {
                    float w = __shfl_sync(0xffffffffu, att[half][r], j);
                    oo[r].x += w * sj.x; oo[r].y += w * sj.y;
                    oo[r].z += w * sj.z; oo[r].w += w * sj.w;
                }
            }
        }
        __syncthreads();   // all old-S reads complete before writes

        // ===== blend (alpha) + beta logit, fused =====
        {
            float4 va = *reinterpret_cast<const float4*>(&V2A[lane * 4]);
            float4 vb = *reinterpret_cast<const float4*>(&V2B[lane * 4]);
            float4 st = *reinterpret_cast<const float4*>(&STAR[lane * 4]);
            #pragma unroll
            for (int r = 0; r < 8; r++) {
                int i = rowBase + r;
                float4 tv = oo[r];
                float part = tv.x * va.x + tv.y * va.y + tv.z * va.z + tv.w * va.w;
                #pragma unroll
                for (int o = 16; o > 0; o >>= 1) part += __shfl_xor_sync(0xffffffffu, part, o);
                float al2 = part * RSQ;
                float4 ns;
                ns.x = (1.f - al2) * tv.x + al2 * st.x;
                ns.y = (1.f - al2) * tv.y + al2 * st.y;
                ns.z = (1.f - al2) * tv.z + al2 * st.z;
                ns.w = (1.f - al2) * tv.w + al2 * st.w;
                *reinterpret_cast<float4*>(&S[i * NPAD + lane * 4]) = ns;
                float pb = ns.x * vb.x + ns.y * vb.y + ns.z * vb.z + ns.w * vb.w;
                #pragma unroll
                for (int o = 16; o > 0; o >>= 1) pb += __shfl_xor_sync(0xffffffffu, pb, o);
                if (lane == 0)
                    BR[i] = (MS[i] == 0.f) ? __int_as_float(0xff800000) : pb * RSQ;
            }
        }
        __syncthreads();

        // ===== beta softmax + star update =====
        if (warp == 0) {
            float l0 = BR[lane], l1 = BR[lane + 32];
            float m = fmaxf(l0, l1);
            #pragma unroll
            for (int o = 16; o > 0; o >>= 1) m = fmaxf(m, __shfl_xor_sync(0xffffffffu, m, o));
            float e0 = __expf(l0 - m), e1 = __expf(l1 - m);
            float sE = e0 + e1;
            #pragma unroll
            for (int o = 16; o > 0; o >>= 1) sE += __shfl_xor_sync(0xffffffffu, sE, o);
            float inv = 1.f / sE;
            BR[lane] = e0 * inv; BR[lane + 32] = e1 * inv;
        }
        __syncthreads();
        if (tid < 128) {
            float acc = 0.f;
            #pragma unroll 8
            for (int j = 0; j < 64; j++) acc += BR[j] * S[j * NPAD + tid];
            STAR[tid] = acc;
        }
        __syncthreads();
    }

    // ===== gate =====
    float* U = sm + OFF_TILE;
    float av[8][4];
    #pragma unroll
    for (int r = 0; r < 8; r++)
        #pragma unroll
        for (int q = 0; q < 4; q++) av[r][q] = 0.f;

    for (int cch = 0; cch < 8; cch++) {
        const int c0 = cch * 32;
        __syncthreads();
        for (int idx = tid; idx < 1024; idx += 256) {
            int doo = idx >> 3, cc4 = idx & 7;
            float4 w = __ldg(reinterpret_cast<const float4*>(&wlin[doo * 256 + c0 + cc4 * 4]));
            *reinterpret_cast<float4*>(&U[doo * 36 + cc4 * 4]) = w;
        }
        __syncthreads();
        const bool firstHalf = (c0 < 128);
        const int cb = firstHalf ? c0 : (c0 - 128);
        #pragma unroll
        for (int cc4 = 0; cc4 < 8; cc4++) {
            float4 cv[8];
            #pragma unroll
            for (int r = 0; r < 8; r++) {
                if (firstHalf)
                    cv[r] = __ldg(reinterpret_cast<const float4*>(&hg[(rowBase + r) * 128 + cb + cc4 * 4]));
                else
                    cv[r] = *reinterpret_cast<const float4*>(&S[(rowBase + r) * NPAD + cb + cc4 * 4]);
            }
            #pragma unroll
            for (int s = 0; s < 4; s++) {
                float4 w4 = *reinterpret_cast<const float4*>(&U[(lane + 32 * s) * 36 + cc4 * 4]);
                #pragma unroll
                for (int r = 0; r < 8; r++)
                    av[r][s] += cv[r].x * w4.x + cv[r].y * w4.y + cv[r].z * w4.z + cv[r].w * w4.w;
            }
        }
    }
    __syncthreads();

    float* ob = outp + (size_t)b * (NN * 128);
    #pragma unroll
    for (int r = 0; r < 8; r++) {
        int i = rowBase + r;
        #pragma unroll
        for (int s = 0; s < 4; s++) {
            int o = lane + 32 * s;
            float g = 1.f / (1.f + __expf(-av[r][s]));
            ob[i * 128 + o] = g * __ldg(&hg[i * 128 + o]) + (1.f - g) * S[i * NPAD + o];
        }
    }
    if (tid < 128) starp[(size_t)b * 128 + tid] = STAR[tid];
}

extern "C" void kernel_launch(void* const* d_in, const int* in_sizes, int n_in,
                              void* d_out, int out_size) {
    float* outp  = (float*)d_out;
    float* starp = outp + (size_t)NB * NN * 128;

    cudaFuncSetAttribute(star_agg_kernel, cudaFuncAttributeMaxDynamicSharedMemorySize, SM_BYTES);
    star_agg_kernel<<<NB, 256, SM_BYTES>>>(
        (const float*)d_in[0], (const int*)d_in[1], (const float*)d_in[2],
        (const float*)d_in[3], (const float*)d_in[4], (const float*)d_in[5], (const float*)d_in[6],
        (const float*)d_in[7], (const float*)d_in[8], (const float*)d_in[9], (const float*)d_in[10],
        (const float*)d_in[11], outp, starp);
}

// round 7
// speedup vs baseline: 1.6137x; 1.2857x over previous
#include <cuda_runtime.h>
#include <cuda_bf16.h>
#include <cstdint>

#define NB   2048
#define NN   64
#define NPAD 132
#define LP   65
#define NEG_BIG (-9000000000000000.0f)

// smem float offsets
#define OFF_S    0          // 64*132 fp32 sate
#define OFF_TILE 8448       // MMA tiles (e-logit: 34816B) | gate W tiles (36864B, spills into dead L)
#define OFF_L    17152      // 64*65 logits
#define OFF_A    21312      // 4*128 a_k
#define OFF_STAR 21824
#define OFF_V1A  21952
#define OFF_V2A  22080
#define OFF_V1B  22208
#define OFF_V2B  22336
#define OFF_MS   22464
#define OFF_BR   22528
#define SM_FLOATS 22592
#define SM_BYTES (SM_FLOATS*4 + 64*68)

#define TSTRIDE_B 272        // 136 bf16 per row (e-logit tiles)
#define TILE_HALF 17408      // bytes: hi tile size (lo at +17408)

#define GWS    144           // gate W tile row stride (bytes)
#define GWHALF (128*144)     // gate W lo offset

__device__ __forceinline__ uint32_t smem_u32(const void* p) {
    uint32_t a;
    asm("{ .reg .u64 t; cvta.to.shared.u64 t, %1; cvt.u32.u64 %0, t; }" : "=r"(a) : "l"(p));
    return a;
}
__device__ __forceinline__ uint32_t pack_bf2(__nv_bfloat16 a, __nv_bfloat16 b) {
    __nv_bfloat162 v = __halves2bfloat162(a, b);
    return *reinterpret_cast<uint32_t*>(&v);
}
__device__ __forceinline__ void cvt_hilo(float2 v, uint32_t& hi, uint32_t& lo) {
    __nv_bfloat16 h0 = __float2bfloat16_rn(v.x), h1 = __float2bfloat16_rn(v.y);
    hi = pack_bf2(h0, h1);
    lo = pack_bf2(__float2bfloat16_rn(v.x - __bfloat162float(h0)),
                  __float2bfloat16_rn(v.y - __bfloat162float(h1)));
}

#define LDSM4(r, addr) \
    asm volatile("ldmatrix.sync.aligned.m8n8.x4.shared.b16 {%0,%1,%2,%3}, [%4];" \
        : "=r"((r)[0]), "=r"((r)[1]), "=r"((r)[2]), "=r"((r)[3]) : "r"(addr))
#define LDSM2(r0, r1, addr) \
    asm volatile("ldmatrix.sync.aligned.m8n8.x2.shared.b16 {%0,%1}, [%2];" \
        : "=r"(r0), "=r"(r1) : "r"(addr))
#define MMA16816(c0,c1,c2,c3, a, b0,b1) \
    asm volatile("mma.sync.aligned.m16n8k16.row.col.f32.bf16.bf16.f32 " \
        "{%0,%1,%2,%3}, {%4,%5,%6,%7}, {%8,%9}, {%0,%1,%2,%3};" \
        : "+f"(c0), "+f"(c1), "+f"(c2), "+f"(c3) \
        : "r"((a)[0]), "r"((a)[1]), "r"((a)[2]), "r"((a)[3]), "r"(b0), "r"(b1))

__device__ __forceinline__ void build_tile(const float* S, const float* vec,
                                           char* tile, int tid) {
    for (int p = tid; p < 4096; p += 256) {
        int row = p >> 6;
        int d = (p & 63) << 1;
        float2 sv = *reinterpret_cast<const float2*>(&S[row * NPAD + d]);
        float x0 = sv.x, x1 = sv.y;
        if (vec) { x0 *= vec[d]; x1 *= vec[d + 1]; }
        uint32_t hi, lo;
        cvt_hilo(make_float2(x0, x1), hi, lo);
        int off = row * TSTRIDE_B + d * 2;
        *reinterpret_cast<uint32_t*>(tile + off)             = hi;
        *reinterpret_cast<uint32_t*>(tile + TILE_HALF + off) = lo;
    }
}

__global__ void __launch_bounds__(256, 2)
star_agg_kernel(const float* __restrict__ hidden, const int* __restrict__ adj,
                const float* __restrict__ mask,
                const float* __restrict__ a0, const float* __restrict__ a1,
                const float* __restrict__ a2, const float* __restrict__ a3,
                const float* __restrict__ q1, const float* __restrict__ k1,
                const float* __restrict__ q2, const float* __restrict__ k2,
                const float* __restrict__ wlin,
                float* __restrict__ outp, float* __restrict__ starp)
{
    extern __shared__ float sm[];
    float* S    = sm + OFF_S;
    float* L    = sm + OFF_L;
    float* A    = sm + OFF_A;
    float* STAR = sm + OFF_STAR;
    float* V1A  = sm + OFF_V1A;
    float* V2A  = sm + OFF_V2A;
    float* V1B  = sm + OFF_V1B;
    float* V2B  = sm + OFF_V2B;
    float* MS   = sm + OFF_MS;
    float* BR   = sm + OFF_BR;
    char*  TILE = (char*)(sm + OFF_TILE);
    unsigned char* ADJ = (unsigned char*)(sm + SM_FLOATS);  // [i][j] stride 68

    const int tid  = threadIdx.x;
    const int lane = tid & 31;
    const int warp = tid >> 5;
    const int b    = blockIdx.x;
    const int rowBase = warp * 8;

    const uint32_t smb   = smem_u32(sm);
    const uint32_t TILEH = smb + OFF_TILE * 4;
    const float* hg = hidden + (size_t)b * (NN * 128);
    const int*   ag = adj    + (size_t)b * (NN * NN);

    for (int idx = tid; idx < NN * 128 / 4; idx += 256) {
        int i = idx >> 5, c4 = (idx & 31) << 2;
        *reinterpret_cast<float4*>(&S[i * NPAD + c4]) = reinterpret_cast<const float4*>(hg)[idx];
    }
    for (int idx = tid; idx < NN * NN; idx += 256)
        ADJ[(idx >> 6) * 68 + (idx & 63)] = (unsigned char)ag[idx];
    if (tid < 128) {
        A[tid] = a0[tid]; A[128 + tid] = a1[tid];
        A[256 + tid] = a2[tid]; A[384 + tid] = a3[tid];
    }
    if (tid < 64) MS[tid] = mask[b * NN + tid];
    __syncthreads();

    if (tid < 128) {
        float acc = 0.f, msum = 0.f;
        #pragma unroll 8
        for (int i = 0; i < NN; i++) { acc += S[i * NPAD + tid] * MS[i]; msum += MS[i]; }
        STAR[tid] = acc / msum;
    }
    __syncthreads();

    const float RSQ = 0.088388347648318447f;
    const int mstrip = warp & 3;
    const int nhalf  = warp >> 2;
    const int R0 = mstrip * 16;
    const int N0 = nhalf * 32;

    for (int step = 0; step < 2; step++) {
        // ===== alpha/beta mat-vecs (depend only on STAR) — both pairs in parallel =====
        {
            const int g = warp >> 2;
            const int t = tid & 127;
            const float* M1 = g ? q2 : k1;
            const float* M2 = g ? k2 : q1;
            float* V1g = g ? V1B : V1A;
            float* V2g = g ? V2B : V2A;
            float s0 = 0.f, s1 = 0.f, s2 = 0.f, s3 = 0.f;
            #pragma unroll 8
            for (int c = 0; c < 128; c += 4) {
                s0 += STAR[c]     * M1[c * 128 + t];
                s1 += STAR[c + 1] * M1[(c + 1) * 128 + t];
                s2 += STAR[c + 2] * M1[(c + 2) * 128 + t];
                s3 += STAR[c + 3] * M1[(c + 3) * 128 + t];
            }
            V1g[t] = (s0 + s1) + (s2 + s3);
            asm volatile("bar.sync %0, 128;" :: "r"(g + 1) : "memory");
            float acc = 0.f;
            const float4* mr = reinterpret_cast<const float4*>(M2 + t * 128);
            #pragma unroll 8
            for (int d4 = 0; d4 < 32; d4++) {
                float4 mv = mr[d4];
                float4 vv = *reinterpret_cast<const float4*>(&V1g[d4 * 4]);
                acc += mv.x * vv.x + mv.y * vv.y + mv.z * vv.z + mv.w * vv.w;
            }
            V2g[t] = acc;
        }

        // ===== build X = S (hi/lo) + init L =====
        build_tile(S, nullptr, TILE, tid);
        for (int p = tid; p < NN * LP; p += 256) L[p] = NEG_BIG;
        __syncthreads();

        // ===== A fragments (held in regs for the step) =====
        uint32_t ah[32], al[32];
        {
            int m4 = lane >> 3;
            uint32_t abase = TILEH + (uint32_t)(R0 + (lane & 7) + ((m4 & 1) << 3)) * TSTRIDE_B
                           + ((m4 >> 1) << 4);
            #pragma unroll
            for (int kt = 0; kt < 8; kt++) {
                LDSM4(&ah[kt * 4], abase + kt * 32);
                LDSM4(&al[kt * 4], abase + TILE_HALF + kt * 32);
            }
        }
        __syncthreads();

        // ===== per edge type: build Y_k, MMA, select =====
        const int lsel = lane & 15;
        const uint32_t bbase = TILEH + (uint32_t)(N0 + (lsel & 7)) * TSTRIDE_B
                             + ((lsel >> 3) << 4);
        for (int k = 0; k < 4; k++) {
            build_tile(S, A + k * 128, TILE, tid);
            __syncthreads();
            #pragma unroll
            for (int nt = 0; nt < 4; nt++) {
                float c0 = 0.f, c1 = 0.f, c2 = 0.f, c3 = 0.f;
                #pragma unroll
                for (int kt = 0; kt < 8; kt++) {
                    uint32_t bh0, bh1, bl0, bl1;
                    uint32_t ba = bbase + nt * (8 * TSTRIDE_B) + kt * 32;
                    LDSM2(bh0, bh1, ba);
                    LDSM2(bl0, bl1, ba + TILE_HALF);
                    MMA16816(c0, c1, c2, c3, &ah[kt * 4], bh0, bh1);
                    MMA16816(c0, c1, c2, c3, &ah[kt * 4], bl0, bl1);
                    MMA16816(c0, c1, c2, c3, &al[kt * 4], bh0, bh1);
                }
                int i0 = R0 + (lane >> 2);
                int j0 = N0 + nt * 8 + ((lane & 3) << 1);
                int code = k + 1;
                if (ADJ[i0 * 68 + j0] == code)
                    L[i0 * LP + j0] = (c0 >= 0.f) ? c0 : 0.2f * c0;
                if (ADJ[i0 * 68 + j0 + 1] == code)
                    L[i0 * LP + j0 + 1] = (c1 >= 0.f) ? c1 : 0.2f * c1;
                if (ADJ[(i0 + 8) * 68 + j0] == code)
                    L[(i0 + 8) * LP + j0] = (c2 >= 0.f) ? c2 : 0.2f * c2;
                if (ADJ[(i0 + 8) * 68 + j0 + 1] == code)
                    L[(i0 + 8) * LP + j0 + 1] = (c3 >= 0.f) ? c3 : 0.2f * c3;
            }
            __syncthreads();
        }

        // ===== row softmax =====
        float att[2][8];
        #pragma unroll
        for (int r = 0; r < 8; r++) {
            int i = rowBase + r;
            float l0 = L[i * LP + lane], l1 = L[i * LP + lane + 32];
            float m = fmaxf(l0, l1);
            #pragma unroll
            for (int o = 16; o > 0; o >>= 1) m = fmaxf(m, __shfl_xor_sync(0xffffffffu, m, o));
            float e0 = __expf(l0 - m), e1 = __expf(l1 - m);
            float sE = e0 + e1;
            #pragma unroll
            for (int o = 16; o > 0; o >>= 1) sE += __shfl_xor_sync(0xffffffffu, sE, o);
            float inv = 1.f / sE;
            att[0][r] = e0 * inv; att[1][r] = e1 * inv;
        }

        // ===== att @ S in registers =====
        float4 oo[8];
        #pragma unroll
        for (int r = 0; r < 8; r++) oo[r] = make_float4(0.f, 0.f, 0.f, 0.f);
        #pragma unroll
        for (int half = 0; half < 2; half++) {
            for (int j = 0; j < 32; j++) {
                float4 sj = *reinterpret_cast<const float4*>(&S[(half * 32 + j) * NPAD + lane * 4]);
                #pragma unroll
                for (int r = 0; r < 8; r++) {
                    float w = __shfl_sync(0xffffffffu, att[half][r], j);
                    oo[r].x += w * sj.x; oo[r].y += w * sj.y;
                    oo[r].z += w * sj.z; oo[r].w += w * sj.w;
                }
            }
        }
        __syncthreads();

        // ===== blend (alpha) + beta logit, fused =====
        {
            float4 va = *reinterpret_cast<const float4*>(&V2A[lane * 4]);
            float4 vb = *reinterpret_cast<const float4*>(&V2B[lane * 4]);
            float4 st = *reinterpret_cast<const float4*>(&STAR[lane * 4]);
            #pragma unroll
            for (int r = 0; r < 8; r++) {
                int i = rowBase + r;
                float4 tv = oo[r];
                float part = tv.x * va.x + tv.y * va.y + tv.z * va.z + tv.w * va.w;
                #pragma unroll
                for (int o = 16; o > 0; o >>= 1) part += __shfl_xor_sync(0xffffffffu, part, o);
                float al2 = part * RSQ;
                float4 ns;
                ns.x = (1.f - al2) * tv.x + al2 * st.x;
                ns.y = (1.f - al2) * tv.y + al2 * st.y;
                ns.z = (1.f - al2) * tv.z + al2 * st.z;
                ns.w = (1.f - al2) * tv.w + al2 * st.w;
                *reinterpret_cast<float4*>(&S[i * NPAD + lane * 4]) = ns;
                float pb = ns.x * vb.x + ns.y * vb.y + ns.z * vb.z + ns.w * vb.w;
                #pragma unroll
                for (int o = 16; o > 0; o >>= 1) pb += __shfl_xor_sync(0xffffffffu, pb, o);
                if (lane == 0)
                    BR[i] = (MS[i] == 0.f) ? __int_as_float(0xff800000) : pb * RSQ;
            }
        }
        __syncthreads();

        // ===== beta softmax + star update =====
        if (warp == 0) {
            float l0 = BR[lane], l1 = BR[lane + 32];
            float m = fmaxf(l0, l1);
            #pragma unroll
            for (int o = 16; o > 0; o >>= 1) m = fmaxf(m, __shfl_xor_sync(0xffffffffu, m, o));
            float e0 = __expf(l0 - m), e1 = __expf(l1 - m);
            float sE = e0 + e1;
            #pragma unroll
            for (int o = 16; o > 0; o >>= 1) sE += __shfl_xor_sync(0xffffffffu, sE, o);
            float inv = 1.f / sE;
            BR[lane] = e0 * inv; BR[lane + 32] = e1 * inv;
        }
        __syncthreads();
        if (tid < 128) {
            float acc = 0.f;
            #pragma unroll 8
            for (int j = 0; j < 64; j++) acc += BR[j] * S[j * NPAD + tid];
            STAR[tid] = acc;
        }
        __syncthreads();
    }

    // ===== gate via MMA: C = cat(hidden,S) @ W^T, K chunked x4 =====
    {
        char* WT = (char*)(sm + OFF_TILE);     // W tile hi (stride 144B), lo at +GWHALF; spans dead TILE+L
        const uint32_t WTH = smb + OFF_TILE * 4;
        const int N0g = nhalf * 64;
        const int lsel = lane & 15;
        float acc[8][4];
        #pragma unroll
        for (int nt = 0; nt < 8; nt++)
            #pragma unroll
            for (int q = 0; q < 4; q++) acc[nt][q] = 0.f;

        for (int chunk = 0; chunk < 4; chunk++) {
            const int c0 = chunk * 64;
            __syncthreads();
            for (int idx = tid; idx < 4096; idx += 256) {
                int o = idx >> 5, p = idx & 31;
                float2 w = __ldg(reinterpret_cast<const float2*>(&wlin[o * 256 + c0 + p * 2]));
                uint32_t hi, lo;
                cvt_hilo(w, hi, lo);
                *reinterpret_cast<uint32_t*>(WT + o * GWS + p * 4)          = hi;
                *reinterpret_cast<uint32_t*>(WT + GWHALF + o * GWS + p * 4) = lo;
            }
            __syncthreads();
            const bool fh = chunk < 2;
            const int cb = fh ? c0 : (c0 - 128);
            const int r0 = R0 + (lane >> 2);
            #pragma unroll
            for (int kt = 0; kt < 4; kt++) {
                int cc = cb + kt * 16 + ((lane & 3) << 1);
                float2 x00, x10, x01, x11;
                if (fh) {
                    x00 = __ldg(reinterpret_cast<const float2*>(&hg[r0 * 128 + cc]));
                    x10 = __ldg(reinterpret_cast<const float2*>(&hg[(r0 + 8) * 128 + cc]));
                    x01 = __ldg(reinterpret_cast<const float2*>(&hg[r0 * 128 + cc + 8]));
                    x11 = __ldg(reinterpret_cast<const float2*>(&hg[(r0 + 8) * 128 + cc + 8]));
                } else {
                    x00 = *reinterpret_cast<const float2*>(&S[r0 * NPAD + cc]);
                    x10 = *reinterpret_cast<const float2*>(&S[(r0 + 8) * NPAD + cc]);
                    x01 = *reinterpret_cast<const float2*>(&S[r0 * NPAD + cc + 8]);
                    x11 = *reinterpret_cast<const float2*>(&S[(r0 + 8) * NPAD + cc + 8]);
                }
                uint32_t fah[4], fal[4];
                cvt_hilo(x00, fah[0], fal[0]);
                cvt_hilo(x10, fah[1], fal[1]);
                cvt_hilo(x01, fah[2], fal[2]);
                cvt_hilo(x11, fah[3], fal[3]);
                uint32_t bb = WTH + (uint32_t)(N0g + (lsel & 7)) * GWS
                            + ((lsel >> 3) << 4) + kt * 32;
                #pragma unroll
                for (int nt = 0; nt < 8; nt++) {
                    uint32_t bh0, bh1, bl0, bl1;
                    uint32_t ba = bb + nt * (8 * GWS);
                    LDSM2(bh0, bh1, ba);
                    LDSM2(bl0, bl1, ba + GWHALF);
                    MMA16816(acc[nt][0], acc[nt][1], acc[nt][2], acc[nt][3], fah, bh0, bh1);
                    MMA16816(acc[nt][0], acc[nt][1], acc[nt][2], acc[nt][3], fah, bl0, bl1);
                    MMA16816(acc[nt][0], acc[nt][1], acc[nt][2], acc[nt][3], fal, bh0, bh1);
                }
            }
        }

        // epilogue: sigmoid + blend, write out
        float* ob = outp + (size_t)b * (NN * 128);
        const int r0 = R0 + (lane >> 2);
        #pragma unroll
        for (int nt = 0; nt < 8; nt++) {
            int o0 = N0g + nt * 8 + ((lane & 3) << 1);
            float2 h0 = __ldg(reinterpret_cast<const float2*>(&hg[r0 * 128 + o0]));
            float2 s0 = *reinterpret_cast<const float2*>(&S[r0 * NPAD + o0]);
            float2 h1 = __ldg(reinterpret_cast<const float2*>(&hg[(r0 + 8) * 128 + o0]));
            float2 s1 = *reinterpret_cast<const float2*>(&S[(r0 + 8) * NPAD + o0]);
            float g00 = 1.f / (1.f + __expf(-acc[nt][0]));
            float g01 = 1.f / (1.f + __expf(-acc[nt][1]));
            float g10 = 1.f / (1.f + __expf(-acc[nt][2]));
            float g11 = 1.f / (1.f + __expf(-acc[nt][3]));
            float2 r0v, r1v;
            r0v.x = g00 * h0.x + (1.f - g00) * s0.x;
            r0v.y = g01 * h0.y + (1.f - g01) * s0.y;
            r1v.x = g10 * h1.x + (1.f - g10) * s1.x;
            r1v.y = g11 * h1.y + (1.f - g11) * s1.y;
            *reinterpret_cast<float2*>(&ob[r0 * 128 + o0])       = r0v;
            *reinterpret_cast<float2*>(&ob[(r0 + 8) * 128 + o0]) = r1v;
        }
    }
    if (tid < 128) starp[(size_t)b * 128 + tid] = STAR[tid];
}

extern "C" void kernel_launch(void* const* d_in, const int* in_sizes, int n_in,
                              void* d_out, int out_size) {
    float* outp  = (float*)d_out;
    float* starp = outp + (size_t)NB * NN * 128;

    cudaFuncSetAttribute(star_agg_kernel, cudaFuncAttributeMaxDynamicSharedMemorySize, SM_BYTES);
    star_agg_kernel<<<NB, 256, SM_BYTES>>>(
        (const float*)d_in[0], (const int*)d_in[1], (const float*)d_in[2],
        (const float*)d_in[3], (const float*)d_in[4], (const float*)d_in[5], (const float*)d_in[6],
        (const float*)d_in[7], (const float*)d_in[8], (const float*)d_in[9], (const float*)d_in[10],
        (const float*)d_in[11], outp, starp);
}

// round 8
// speedup vs baseline: 2.1110x; 1.3082x over previous
#include <cuda_runtime.h>
#include <cuda_bf16.h>
#include <cstdint>

#define NB   2048
#define NN   64
#define NPAD 132
#define LP   65
#define NEG_BIG (-9000000000000000.0f)

// smem float offsets
#define OFF_S    0          // 64*132 fp32 sate
#define OFF_TILE 8448       // MMA tiles (34816B) | gate W tiles (36864B)
#define OFF_L    17152      // logits 64*65 | att bf16 tile hi/lo (18432B, clobbers A)
#define OFF_A    21312      // 4*128 a_k (reloaded per step)
#define OFF_STAR 21824
#define OFF_V2A  22080
#define OFF_V2B  22336
#define OFF_MS   22464
#define OFF_BR   22528
#define OFF_PA   22592      // 64*2 alpha partials
#define OFF_PB   22720      // 64*2 beta partials
#define SM_FLOATS 22848
#define SM_BYTES (SM_FLOATS*4 + 64*68)

#define TSTRIDE_B 272        // 136 bf16 per row (S/Y tiles)
#define TILE_HALF 17408      // hi tile bytes (lo at +17408)
#define ATT_S     144        // att tile row stride bytes
#define ATT_HALF  9216       // att hi tile bytes

#define GWS    144           // gate W tile row stride
#define GWHALF (128*144)

__device__ float g_M1T[16384];   // (q1 @ k1^T)^T, column-major access
__device__ float g_M2T[16384];   // (k2 @ q2^T)^T

__device__ __forceinline__ uint32_t smem_u32(const void* p) {
    uint32_t a;
    asm("{ .reg .u64 t; cvta.to.shared.u64 t, %1; cvt.u32.u64 %0, t; }" : "=r"(a) : "l"(p));
    return a;
}
__device__ __forceinline__ uint32_t pack_bf2(__nv_bfloat16 a, __nv_bfloat16 b) {
    __nv_bfloat162 v = __halves2bfloat162(a, b);
    return *reinterpret_cast<uint32_t*>(&v);
}
__device__ __forceinline__ void cvt_hilo(float2 v, uint32_t& hi, uint32_t& lo) {
    __nv_bfloat16 h0 = __float2bfloat16_rn(v.x), h1 = __float2bfloat16_rn(v.y);
    hi = pack_bf2(h0, h1);
    lo = pack_bf2(__float2bfloat16_rn(v.x - __bfloat162float(h0)),
                  __float2bfloat16_rn(v.y - __bfloat162float(h1)));
}

#define LDSM4(r, addr) \
    asm volatile("ldmatrix.sync.aligned.m8n8.x4.shared.b16 {%0,%1,%2,%3}, [%4];" \
        : "=r"((r)[0]), "=r"((r)[1]), "=r"((r)[2]), "=r"((r)[3]) : "r"(addr))
#define LDSM2(r0, r1, addr) \
    asm volatile("ldmatrix.sync.aligned.m8n8.x2.shared.b16 {%0,%1}, [%2];" \
        : "=r"(r0), "=r"(r1) : "r"(addr))
#define LDSM2T(r0, r1, addr) \
    asm volatile("ldmatrix.sync.aligned.m8n8.x2.trans.shared.b16 {%0,%1}, [%2];" \
        : "=r"(r0), "=r"(r1) : "r"(addr))
#define MMA16816(c0,c1,c2,c3, a, b0,b1) \
    asm volatile("mma.sync.aligned.m16n8k16.row.col.f32.bf16.bf16.f32 " \
        "{%0,%1,%2,%3}, {%4,%5,%6,%7}, {%8,%9}, {%0,%1,%2,%3};" \
        : "+f"(c0), "+f"(c1), "+f"(c2), "+f"(c3) \
        : "r"((a)[0]), "r"((a)[1]), "r"((a)[2]), "r"((a)[3]), "r"(b0), "r"(b1))

__device__ __forceinline__ void build_tile(const float* S, const float* vec,
                                           char* tile, int tid) {
    for (int p = tid; p < 4096; p += 256) {
        int row = p >> 6;
        int d = (p & 63) << 1;
        float2 sv = *reinterpret_cast<const float2*>(&S[row * NPAD + d]);
        float x0 = sv.x, x1 = sv.y;
        if (vec) { x0 *= vec[d]; x1 *= vec[d + 1]; }
        uint32_t hi, lo;
        cvt_hilo(make_float2(x0, x1), hi, lo);
        int off = row * TSTRIDE_B + d * 2;
        *reinterpret_cast<uint32_t*>(tile + off)             = hi;
        *reinterpret_cast<uint32_t*>(tile + TILE_HALF + off) = lo;
    }
}

// ---- prep: M1 = q1@k1^T, M2 = k2@q2^T, stored transposed ----
__global__ void prep_kernel(const float* __restrict__ q1, const float* __restrict__ k1,
                            const float* __restrict__ q2, const float* __restrict__ k2) {
    int o = blockIdx.x * 256 + threadIdx.x;     // 0..32767
    int m = o >> 14;
    int idx = o & 16383;
    int t = idx >> 7;
    int c = idx & 127;
    const float* X = m ? k2 : q1;
    const float* Y = m ? q2 : k1;
    float acc = 0.f;
    const float4* xr = reinterpret_cast<const float4*>(X + t * 128);
    const float4* yr = reinterpret_cast<const float4*>(Y + c * 128);
    #pragma unroll 8
    for (int d = 0; d < 32; d++) {
        float4 xv = xr[d], yv = yr[d];
        acc += xv.x * yv.x + xv.y * yv.y + xv.z * yv.z + xv.w * yv.w;
    }
    (m ? g_M2T : g_M1T)[c * 128 + t] = acc;
}

__global__ void __launch_bounds__(256, 2)
star_agg_kernel(const float* __restrict__ hidden, const int* __restrict__ adj,
                const float* __restrict__ mask,
                const float* __restrict__ a0, const float* __restrict__ a1,
                const float* __restrict__ a2, const float* __restrict__ a3,
                const float* __restrict__ wlin,
                float* __restrict__ outp, float* __restrict__ starp)
{
    extern __shared__ float sm[];
    float* S    = sm + OFF_S;
    float* L    = sm + OFF_L;
    float* A    = sm + OFF_A;
    float* STAR = sm + OFF_STAR;
    float* V2A  = sm + OFF_V2A;
    float* V2B  = sm + OFF_V2B;
    float* MS   = sm + OFF_MS;
    float* BR   = sm + OFF_BR;
    float* PA   = sm + OFF_PA;
    float* PB   = sm + OFF_PB;
    char*  TILE = (char*)(sm + OFF_TILE);
    char*  ATT  = (char*)(sm + OFF_L);
    unsigned char* ADJ = (unsigned char*)(sm + SM_FLOATS);  // [i][j] stride 68

    const int tid  = threadIdx.x;
    const int lane = tid & 31;
    const int warp = tid >> 5;
    const int b    = blockIdx.x;
    const int rowBase = warp * 8;

    const uint32_t smb   = smem_u32(sm);
    const uint32_t TILEH = smb + OFF_TILE * 4;
    const uint32_t ATTH  = smb + OFF_L * 4;
    const float* hg = hidden + (size_t)b * (NN * 128);
    const int*   ag = adj    + (size_t)b * (NN * NN);

    for (int idx = tid; idx < NN * 128 / 4; idx += 256) {
        int i = idx >> 5, c4 = (idx & 31) << 2;
        *reinterpret_cast<float4*>(&S[i * NPAD + c4]) = reinterpret_cast<const float4*>(hg)[idx];
    }
    for (int idx = tid; idx < NN * NN; idx += 256)
        ADJ[(idx >> 6) * 68 + (idx & 63)] = (unsigned char)ag[idx];
    if (tid < 64) MS[tid] = mask[b * NN + tid];
    __syncthreads();

    if (tid < 128) {
        float acc = 0.f, msum = 0.f;
        #pragma unroll 8
        for (int i = 0; i < NN; i++) { acc += S[i * NPAD + tid] * MS[i]; msum += MS[i]; }
        STAR[tid] = acc / msum;
    }
    __syncthreads();

    const float RSQ = 0.088388347648318447f;
    const int mstrip = warp & 3;
    const int nhalf  = warp >> 2;
    const int R0 = mstrip * 16;
    const int N0 = nhalf * 32;

    for (int step = 0; step < 2; step++) {
        // ===== single matvec per pair: V2A = M1@star (w0-3), V2B = M2@star (w4-7) =====
        {
            const int g = warp >> 2;
            const int t = tid & 127;
            const float* MT = g ? g_M2T : g_M1T;
            float* V2g = g ? V2B : V2A;
            float s0 = 0.f, s1 = 0.f, s2 = 0.f, s3 = 0.f;
            #pragma unroll 8
            for (int c = 0; c < 128; c += 4) {
                s0 += STAR[c]     * MT[c * 128 + t];
                s1 += STAR[c + 1] * MT[(c + 1) * 128 + t];
                s2 += STAR[c + 2] * MT[(c + 2) * 128 + t];
                s3 += STAR[c + 3] * MT[(c + 3) * 128 + t];
            }
            V2g[t] = (s0 + s1) + (s2 + s3);
        }
        // reload a_k (att tile clobbered A last step)
        for (int idx = tid; idx < 512; idx += 256) {
            const float* src = (idx < 128) ? a0 : (idx < 256) ? a1 : (idx < 384) ? a2 : a3;
            A[idx] = src[idx & 127];
        }

        // ===== build X = S (hi/lo) + init L =====
        build_tile(S, nullptr, TILE, tid);
        for (int p = tid; p < NN * LP; p += 256) L[p] = NEG_BIG;
        __syncthreads();

        // ===== A fragments (X) held in regs =====
        uint32_t ah[32], al[32];
        {
            int m4 = lane >> 3;
            uint32_t abase = TILEH + (uint32_t)(R0 + (lane & 7) + ((m4 & 1) << 3)) * TSTRIDE_B
                           + ((m4 >> 1) << 4);
            #pragma unroll
            for (int kt = 0; kt < 8; kt++) {
                LDSM4(&ah[kt * 4], abase + kt * 32);
                LDSM4(&al[kt * 4], abase + TILE_HALF + kt * 32);
            }
        }
        __syncthreads();

        // ===== per edge type: build Y_k, MMA, select =====
        const int lsel = lane & 15;
        const uint32_t bbase = TILEH + (uint32_t)(N0 + (lsel & 7)) * TSTRIDE_B
                             + ((lsel >> 3) << 4);
        for (int k = 0; k < 4; k++) {
            build_tile(S, A + k * 128, TILE, tid);
            __syncthreads();
            #pragma unroll
            for (int nt = 0; nt < 4; nt++) {
                float c0 = 0.f, c1 = 0.f, c2 = 0.f, c3 = 0.f;
                #pragma unroll
                for (int kt = 0; kt < 8; kt++) {
                    uint32_t bh0, bh1, bl0, bl1;
                    uint32_t ba = bbase + nt * (8 * TSTRIDE_B) + kt * 32;
                    LDSM2(bh0, bh1, ba);
                    LDSM2(bl0, bl1, ba + TILE_HALF);
                    MMA16816(c0, c1, c2, c3, &ah[kt * 4], bh0, bh1);
                    MMA16816(c0, c1, c2, c3, &ah[kt * 4], bl0, bl1);
                    MMA16816(c0, c1, c2, c3, &al[kt * 4], bh0, bh1);
                }
                int i0 = R0 + (lane >> 2);
                int j0 = N0 + nt * 8 + ((lane & 3) << 1);
                int code = k + 1;
                if (ADJ[i0 * 68 + j0] == code)
                    L[i0 * LP + j0] = (c0 >= 0.f) ? c0 : 0.2f * c0;
                if (ADJ[i0 * 68 + j0 + 1] == code)
                    L[i0 * LP + j0 + 1] = (c1 >= 0.f) ? c1 : 0.2f * c1;
                if (ADJ[(i0 + 8) * 68 + j0] == code)
                    L[(i0 + 8) * LP + j0] = (c2 >= 0.f) ? c2 : 0.2f * c2;
                if (ADJ[(i0 + 8) * 68 + j0 + 1] == code)
                    L[(i0 + 8) * LP + j0 + 1] = (c3 >= 0.f) ? c3 : 0.2f * c3;
            }
            __syncthreads();
        }

        // ===== row softmax (att in regs) =====
        float att[2][8];
        #pragma unroll
        for (int r = 0; r < 8; r++) {
            int i = rowBase + r;
            float l0 = L[i * LP + lane], l1 = L[i * LP + lane + 32];
            float m = fmaxf(l0, l1);
            #pragma unroll
            for (int o = 16; o > 0; o >>= 1) m = fmaxf(m, __shfl_xor_sync(0xffffffffu, m, o));
            float e0 = __expf(l0 - m), e1 = __expf(l1 - m);
            float sE = e0 + e1;
            #pragma unroll
            for (int o = 16; o > 0; o >>= 1) sE += __shfl_xor_sync(0xffffffffu, sE, o);
            float inv = 1.f / sE;
            att[0][r] = e0 * inv; att[1][r] = e1 * inv;
        }
        __syncthreads();   // everyone done reading L before att tile overwrites it

        // ===== rebuild X tile + write att bf16 tile (over L/A region) =====
        build_tile(S, nullptr, TILE, tid);
        #pragma unroll
        for (int half = 0; half < 2; half++) {
            int c = lane + 32 * half;
            #pragma unroll
            for (int r = 0; r < 8; r++) {
                float v = att[half][r];
                __nv_bfloat16 h = __float2bfloat16_rn(v);
                __nv_bfloat16 l = __float2bfloat16_rn(v - __bfloat162float(h));
                int off = (rowBase + r) * ATT_S + c * 2;
                *reinterpret_cast<__nv_bfloat16*>(ATT + off)            = h;
                *reinterpret_cast<__nv_bfloat16*>(ATT + ATT_HALF + off) = l;
            }
        }
        __syncthreads();

        // ===== T = att @ S via MMA (A = att tile, B = X tile transposed) =====
        {
            uint32_t aah[16], aal[16];
            int m4 = lane >> 3;
            uint32_t abase = ATTH + (uint32_t)(R0 + (lane & 7) + ((m4 & 1) << 3)) * ATT_S
                           + ((m4 >> 1) << 4);
            #pragma unroll
            for (int kt = 0; kt < 4; kt++) {
                LDSM4(&aah[kt * 4], abase + kt * 32);
                LDSM4(&aal[kt * 4], abase + ATT_HALF + kt * 32);
            }
            const int N0d = nhalf * 64;
            float tc[8][4];
            #pragma unroll
            for (int nt = 0; nt < 8; nt++)
                #pragma unroll
                for (int q = 0; q < 4; q++) tc[nt][q] = 0.f;
            #pragma unroll
            for (int nt = 0; nt < 8; nt++) {
                #pragma unroll
                for (int kt = 0; kt < 4; kt++) {
                    uint32_t bh0, bh1, bl0, bl1;
                    uint32_t ba = TILEH + (uint32_t)(kt * 16 + lsel) * TSTRIDE_B
                                + (uint32_t)(N0d + nt * 8) * 2;
                    LDSM2T(bh0, bh1, ba);
                    LDSM2T(bl0, bl1, ba + TILE_HALF);
                    MMA16816(tc[nt][0], tc[nt][1], tc[nt][2], tc[nt][3], &aah[kt * 4], bh0, bh1);
                    MMA16816(tc[nt][0], tc[nt][1], tc[nt][2], tc[nt][3], &aah[kt * 4], bl0, bl1);
                    MMA16816(tc[nt][0], tc[nt][1], tc[nt][2], tc[nt][3], &aal[kt * 4], bh0, bh1);
                }
            }

            // ---- alpha partial dots ----
            const int i0 = R0 + (lane >> 2);
            float pa0 = 0.f, pa1 = 0.f;
            #pragma unroll
            for (int nt = 0; nt < 8; nt++) {
                int d0 = N0d + nt * 8 + ((lane & 3) << 1);
                float2 va = *reinterpret_cast<const float2*>(&V2A[d0]);
                pa0 += tc[nt][0] * va.x + tc[nt][1] * va.y;
                pa1 += tc[nt][2] * va.x + tc[nt][3] * va.y;
            }
            pa0 += __shfl_xor_sync(0xffffffffu, pa0, 1);
            pa0 += __shfl_xor_sync(0xffffffffu, pa0, 2);
            pa1 += __shfl_xor_sync(0xffffffffu, pa1, 1);
            pa1 += __shfl_xor_sync(0xffffffffu, pa1, 2);
            if ((lane & 3) == 0) {
                PA[i0 * 2 + nhalf]       = pa0;
                PA[(i0 + 8) * 2 + nhalf] = pa1;
            }
            __syncthreads();
            float al0 = (PA[i0 * 2] + PA[i0 * 2 + 1]) * RSQ;
            float al1 = (PA[(i0 + 8) * 2] + PA[(i0 + 8) * 2 + 1]) * RSQ;

            // ---- blend + write new S + beta partials ----
            float pb0 = 0.f, pb1 = 0.f;
            #pragma unroll
            for (int nt = 0; nt < 8; nt++) {
                int d0 = N0d + nt * 8 + ((lane & 3) << 1);
                float2 st = *reinterpret_cast<const float2*>(&STAR[d0]);
                float2 vb = *reinterpret_cast<const float2*>(&V2B[d0]);
                float n0x = (1.f - al0) * tc[nt][0] + al0 * st.x;
                float n0y = (1.f - al0) * tc[nt][1] + al0 * st.y;
                float n1x = (1.f - al1) * tc[nt][2] + al1 * st.x;
                float n1y = (1.f - al1) * tc[nt][3] + al1 * st.y;
                *reinterpret_cast<float2*>(&S[i0 * NPAD + d0])       = make_float2(n0x, n0y);
                *reinterpret_cast<float2*>(&S[(i0 + 8) * NPAD + d0]) = make_float2(n1x, n1y);
                pb0 += n0x * vb.x + n0y * vb.y;
                pb1 += n1x * vb.x + n1y * vb.y;
            }
            pb0 += __shfl_xor_sync(0xffffffffu, pb0, 1);
            pb0 += __shfl_xor_sync(0xffffffffu, pb0, 2);
            pb1 += __shfl_xor_sync(0xffffffffu, pb1, 1);
            pb1 += __shfl_xor_sync(0xffffffffu, pb1, 2);
            if ((lane & 3) == 0) {
                PB[i0 * 2 + nhalf]       = pb0;
                PB[(i0 + 8) * 2 + nhalf] = pb1;
            }
        }
        __syncthreads();

        // ===== beta softmax + star update =====
        if (warp == 0) {
            float b0 = (MS[lane] == 0.f)      ? __int_as_float(0xff800000)
                                              : (PB[lane * 2] + PB[lane * 2 + 1]) * RSQ;
            float b1 = (MS[lane + 32] == 0.f) ? __int_as_float(0xff800000)
                                              : (PB[(lane + 32) * 2] + PB[(lane + 32) * 2 + 1]) * RSQ;
            float m = fmaxf(b0, b1);
            #pragma unroll
            for (int o = 16; o > 0; o >>= 1) m = fmaxf(m, __shfl_xor_sync(0xffffffffu, m, o));
            float e0 = __expf(b0 - m), e1 = __expf(b1 - m);
            float sE = e0 + e1;
            #pragma unroll
            for (int o = 16; o > 0; o >>= 1) sE += __shfl_xor_sync(0xffffffffu, sE, o);
            float inv = 1.f / sE;
            BR[lane] = e0 * inv; BR[lane + 32] = e1 * inv;
        }
        __syncthreads();
        if (tid < 128) {
            float acc = 0.f;
            #pragma unroll 8
            for (int j = 0; j < 64; j++) acc += BR[j] * S[j * NPAD + tid];
            STAR[tid] = acc;
        }
        __syncthreads();
    }

    // ===== gate via MMA: C = cat(hidden,S) @ W^T =====
    {
        char* WT = (char*)(sm + OFF_TILE);
        const uint32_t WTH = smb + OFF_TILE * 4;
        const int N0g = nhalf * 64;
        const int lsel = lane & 15;
        float acc[8][4];
        #pragma unroll
        for (int nt = 0; nt < 8; nt++)
            #pragma unroll
            for (int q = 0; q < 4; q++) acc[nt][q] = 0.f;

        for (int chunk = 0; chunk < 4; chunk++) {
            const int c0 = chunk * 64;
            __syncthreads();
            for (int idx = tid; idx < 4096; idx += 256) {
                int o = idx >> 5, p = idx & 31;
                float2 w = __ldg(reinterpret_cast<const float2*>(&wlin[o * 256 + c0 + p * 2]));
                uint32_t hi, lo;
                cvt_hilo(w, hi, lo);
                *reinterpret_cast<uint32_t*>(WT + o * GWS + p * 4)          = hi;
                *reinterpret_cast<uint32_t*>(WT + GWHALF + o * GWS + p * 4) = lo;
            }
            __syncthreads();
            const bool fh = chunk < 2;
            const int cb = fh ? c0 : (c0 - 128);
            const int r0 = R0 + (lane >> 2);
            #pragma unroll
            for (int kt = 0; kt < 4; kt++) {
                int cc = cb + kt * 16 + ((lane & 3) << 1);
                float2 x00, x10, x01, x11;
                if (fh) {
                    x00 = __ldg(reinterpret_cast<const float2*>(&hg[r0 * 128 + cc]));
                    x10 = __ldg(reinterpret_cast<const float2*>(&hg[(r0 + 8) * 128 + cc]));
                    x01 = __ldg(reinterpret_cast<const float2*>(&hg[r0 * 128 + cc + 8]));
                    x11 = __ldg(reinterpret_cast<const float2*>(&hg[(r0 + 8) * 128 + cc + 8]));
                } else {
                    x00 = *reinterpret_cast<const float2*>(&S[r0 * NPAD + cc]);
                    x10 = *reinterpret_cast<const float2*>(&S[(r0 + 8) * NPAD + cc]);
                    x01 = *reinterpret_cast<const float2*>(&S[r0 * NPAD + cc + 8]);
                    x11 = *reinterpret_cast<const float2*>(&S[(r0 + 8) * NPAD + cc + 8]);
                }
                uint32_t fah[4], fal[4];
                cvt_hilo(x00, fah[0], fal[0]);
                cvt_hilo(x10, fah[1], fal[1]);
                cvt_hilo(x01, fah[2], fal[2]);
                cvt_hilo(x11, fah[3], fal[3]);
                uint32_t bb = WTH + (uint32_t)(N0g + (lsel & 7)) * GWS
                            + ((lsel >> 3) << 4) + kt * 32;
                #pragma unroll
                for (int nt = 0; nt < 8; nt++) {
                    uint32_t bh0, bh1, bl0, bl1;
                    uint32_t ba = bb + nt * (8 * GWS);
                    LDSM2(bh0, bh1, ba);
                    LDSM2(bl0, bl1, ba + GWHALF);
                    MMA16816(acc[nt][0], acc[nt][1], acc[nt][2], acc[nt][3], fah, bh0, bh1);
                    MMA16816(acc[nt][0], acc[nt][1], acc[nt][2], acc[nt][3], fah, bl0, bl1);
                    MMA16816(acc[nt][0], acc[nt][1], acc[nt][2], acc[nt][3], fal, bh0, bh1);
                }
            }
        }

        float* ob = outp + (size_t)b * (NN * 128);
        const int r0 = R0 + (lane >> 2);
        #pragma unroll
        for (int nt = 0; nt < 8; nt++) {
            int o0 = N0g + nt * 8 + ((lane & 3) << 1);
            float2 h0 = __ldg(reinterpret_cast<const float2*>(&hg[r0 * 128 + o0]));
            float2 s0 = *reinterpret_cast<const float2*>(&S[r0 * NPAD + o0]);
            float2 h1 = __ldg(reinterpret_cast<const float2*>(&hg[(r0 + 8) * 128 + o0]));
            float2 s1 = *reinterpret_cast<const float2*>(&S[(r0 + 8) * NPAD + o0]);
            float g00 = 1.f / (1.f + __expf(-acc[nt][0]));
            float g01 = 1.f / (1.f + __expf(-acc[nt][1]));
            float g10 = 1.f / (1.f + __expf(-acc[nt][2]));
            float g11 = 1.f / (1.f + __expf(-acc[nt][3]));
            float2 r0v, r1v;
            r0v.x = g00 * h0.x + (1.f - g00) * s0.x;
            r0v.y = g01 * h0.y + (1.f - g01) * s0.y;
            r1v.x = g10 * h1.x + (1.f - g10) * s1.x;
            r1v.y = g11 * h1.y + (1.f - g11) * s1.y;
            *reinterpret_cast<float2*>(&ob[r0 * 128 + o0])       = r0v;
            *reinterpret_cast<float2*>(&ob[(r0 + 8) * 128 + o0]) = r1v;
        }
    }
    if (tid < 128) starp[(size_t)b * 128 + tid] = STAR[tid];
}

extern "C" void kernel_launch(void* const* d_in, const int* in_sizes, int n_in,
                              void* d_out, int out_size) {
    float* outp  = (float*)d_out;
    float* starp = outp + (size_t)NB * NN * 128;

    prep_kernel<<<128, 256>>>((const float*)d_in[7], (const float*)d_in[8],
                              (const float*)d_in[9], (const float*)d_in[10]);

    cudaFuncSetAttribute(star_agg_kernel, cudaFuncAttributeMaxDynamicSharedMemorySize, SM_BYTES);
    star_agg_kernel<<<NB, 256, SM_BYTES>>>(
        (const float*)d_in[0], (const int*)d_in[1], (const float*)d_in[2],
        (const float*)d_in[3], (const float*)d_in[4], (const float*)d_in[5], (const float*)d_in[6],
        (const float*)d_in[11], outp, starp);
}

// round 9
// speedup vs baseline: 2.4869x; 1.1780x over previous
#include <cuda_runtime.h>
#include <cuda_bf16.h>
#include <cstdint>

#define NB   2048
#define NN   64
#define NPAD 132
#define NEG_BIG (-9000000000000000.0f)

#define OFF_S    0          // 64*132 fp32
#define OFF_X    8448       // persistent S bf16 hi/lo tile (34816B)
#define OFF_Y    17152      // Y_k tile | ATT tile | gate W staging (36864B w/ spill into A)
#define OFF_A    25856      // a_k (dead at gate; W spills here)
#define OFF_STAR 26368
#define OFF_V2A  26496
#define OFF_V2B  26624
#define OFF_MS   26752
#define OFF_BR   26816
#define OFF_PA   26880
#define OFF_PB   27008
#define SM_FLOATS 27136
#define SM_BYTES (SM_FLOATS*4 + 64*68)   // 112896

#define TS    272            // X/Y tile row stride bytes
#define THALF 17408
#define ATT_S 144
#define ATT_HALF 9216
#define GWS   144
#define GWHALF (128*144)

__device__ float g_M1T[16384];
__device__ float g_M2T[16384];

__device__ __forceinline__ uint32_t smem_u32(const void* p) {
    uint32_t a;
    asm("{ .reg .u64 t; cvta.to.shared.u64 t, %1; cvt.u32.u64 %0, t; }" : "=r"(a) : "l"(p));
    return a;
}
__device__ __forceinline__ uint32_t pack_bf2(__nv_bfloat16 a, __nv_bfloat16 b) {
    __nv_bfloat162 v = __halves2bfloat162(a, b);
    return *reinterpret_cast<uint32_t*>(&v);
}
__device__ __forceinline__ void cvt_hilo(float2 v, uint32_t& hi, uint32_t& lo) {
    __nv_bfloat16 h0 = __float2bfloat16_rn(v.x), h1 = __float2bfloat16_rn(v.y);
    hi = pack_bf2(h0, h1);
    lo = pack_bf2(__float2bfloat16_rn(v.x - __bfloat162float(h0)),
                  __float2bfloat16_rn(v.y - __bfloat162float(h1)));
}

#define LDSM4(r, addr) \
    asm volatile("ldmatrix.sync.aligned.m8n8.x4.shared.b16 {%0,%1,%2,%3}, [%4];" \
        : "=r"((r)[0]), "=r"((r)[1]), "=r"((r)[2]), "=r"((r)[3]) : "r"(addr))
#define LDSM2(r0, r1, addr) \
    asm volatile("ldmatrix.sync.aligned.m8n8.x2.shared.b16 {%0,%1}, [%2];" \
        : "=r"(r0), "=r"(r1) : "r"(addr))
#define LDSM2T(r0, r1, addr) \
    asm volatile("ldmatrix.sync.aligned.m8n8.x2.trans.shared.b16 {%0,%1}, [%2];" \
        : "=r"(r0), "=r"(r1) : "r"(addr))
#define MMA16816(c0,c1,c2,c3, a, b0,b1) \
    asm volatile("mma.sync.aligned.m16n8k16.row.col.f32.bf16.bf16.f32 " \
        "{%0,%1,%2,%3}, {%4,%5,%6,%7}, {%8,%9}, {%0,%1,%2,%3};" \
        : "+f"(c0), "+f"(c1), "+f"(c2), "+f"(c3) \
        : "r"((a)[0]), "r"((a)[1]), "r"((a)[2]), "r"((a)[3]), "r"(b0), "r"(b1))

__device__ __forceinline__ void build_tile(const float* S, const float* vec,
                                           char* tile, int tid) {
    for (int p = tid; p < 4096; p += 256) {
        int row = p >> 6, d = (p & 63) << 1;
        float2 sv = *reinterpret_cast<const float2*>(&S[row * NPAD + d]);
        float x0 = sv.x, x1 = sv.y;
        if (vec) { x0 *= vec[d]; x1 *= vec[d + 1]; }
        uint32_t hi, lo;
        cvt_hilo(make_float2(x0, x1), hi, lo);
        int off = row * TS + d * 2;
        *reinterpret_cast<uint32_t*>(tile + off)         = hi;
        *reinterpret_cast<uint32_t*>(tile + THALF + off) = lo;
    }
}

__global__ void prep_kernel(const float* __restrict__ q1, const float* __restrict__ k1,
                            const float* __restrict__ q2, const float* __restrict__ k2) {
    int o = blockIdx.x * 256 + threadIdx.x;
    int m = o >> 14, idx = o & 16383;
    int t = idx >> 7, c = idx & 127;
    const float* X = m ? k2 : q1;
    const float* Y = m ? q2 : k1;
    float acc = 0.f;
    const float4* xr = reinterpret_cast<const float4*>(X + t * 128);
    const float4* yr = reinterpret_cast<const float4*>(Y + c * 128);
    #pragma unroll 8
    for (int d = 0; d < 32; d++) {
        float4 xv = xr[d], yv = yr[d];
        acc += xv.x * yv.x + xv.y * yv.y + xv.z * yv.z + xv.w * yv.w;
    }
    (m ? g_M2T : g_M1T)[c * 128 + t] = acc;
}

__global__ void __launch_bounds__(256, 2)
star_agg_kernel(const float* __restrict__ hidden, const int* __restrict__ adj,
                const float* __restrict__ mask,
                const float* __restrict__ a0, const float* __restrict__ a1,
                const float* __restrict__ a2, const float* __restrict__ a3,
                const float* __restrict__ wlin,
                float* __restrict__ outp, float* __restrict__ starp)
{
    extern __shared__ float sm[];
    float* S    = sm + OFF_S;
    float* A    = sm + OFF_A;
    float* STAR = sm + OFF_STAR;
    float* V2A  = sm + OFF_V2A;
    float* V2B  = sm + OFF_V2B;
    float* MS   = sm + OFF_MS;
    float* BR   = sm + OFF_BR;
    float* PA   = sm + OFF_PA;
    float* PB   = sm + OFF_PB;
    char*  XT   = (char*)(sm + OFF_X);
    char*  YT   = (char*)(sm + OFF_Y);
    unsigned char* ADJ = (unsigned char*)(sm + SM_FLOATS);

    const int tid = threadIdx.x, lane = tid & 31, warp = tid >> 5, b = blockIdx.x;
    const uint32_t smb = smem_u32(sm);
    const uint32_t XH = smb + OFF_X * 4;
    const uint32_t YH = smb + OFF_Y * 4;
    const float* hg = hidden + (size_t)b * (NN * 128);
    const int*   ag = adj + (size_t)b * (NN * NN);

    for (int idx = tid; idx < NN * 32; idx += 256) {
        int i = idx >> 5, c4 = (idx & 31) << 2;
        *reinterpret_cast<float4*>(&S[i * NPAD + c4]) = reinterpret_cast<const float4*>(hg)[idx];
    }
    for (int idx = tid; idx < NN * NN; idx += 256)
        ADJ[(idx >> 6) * 68 + (idx & 63)] = (unsigned char)ag[idx];
    if (tid < 128) {
        A[tid] = a0[tid]; A[128 + tid] = a1[tid];
        A[256 + tid] = a2[tid]; A[384 + tid] = a3[tid];
    }
    if (tid < 64) MS[tid] = mask[b * NN + tid];
    __syncthreads();
    build_tile(S, nullptr, (char*)XT, tid);   // persistent X tile
    if (tid < 128) {
        float acc = 0.f, msum = 0.f;
        #pragma unroll 8
        for (int i = 0; i < NN; i++) { acc += S[i * NPAD + tid] * MS[i]; msum += MS[i]; }
        STAR[tid] = acc / msum;
    }
    __syncthreads();

    const float RSQ = 0.088388347648318447f;
    const int mstrip = warp & 3, nhalf = warp >> 2;
    const int R0 = mstrip * 16, N0 = nhalf * 32;
    const int g = lane >> 2, i0 = R0 + g;
    const int lsel = lane & 15;

    for (int step = 0; step < 2; step++) {
        // ===== star matvecs (parallel pairs) =====
        {
            const int gg = warp >> 2;
            const int t = tid & 127;
            const float* MT = gg ? g_M2T : g_M1T;
            float* V2g = gg ? V2B : V2A;
            float s0 = 0.f, s1 = 0.f, s2 = 0.f, s3 = 0.f;
            #pragma unroll 8
            for (int c = 0; c < 128; c += 4) {
                s0 += STAR[c]     * MT[c * 128 + t];
                s1 += STAR[c + 1] * MT[(c + 1) * 128 + t];
                s2 += STAR[c + 2] * MT[(c + 2) * 128 + t];
                s3 += STAR[c + 3] * MT[(c + 3) * 128 + t];
            }
            V2g[t] = (s0 + s1) + (s2 + s3);
        }
        __syncthreads();

        // ===== A frags (X tile, current S) =====
        uint32_t ah[32], al[32];
        {
            int m4 = lane >> 3;
            uint32_t abase = XH + (uint32_t)(R0 + (lane & 7) + ((m4 & 1) << 3)) * TS
                           + ((m4 >> 1) << 4);
            #pragma unroll
            for (int kt = 0; kt < 8; kt++) {
                LDSM4(&ah[kt * 4], abase + kt * 32);
                LDSM4(&al[kt * 4], abase + THALF + kt * 32);
            }
        }

        // ===== e-logits: per k build Y, MMA, reg-select =====
        float sel[4][4];
        #pragma unroll
        for (int nt = 0; nt < 4; nt++)
            #pragma unroll
            for (int q = 0; q < 4; q++) sel[nt][q] = NEG_BIG;
        const uint32_t bbase = YH + (uint32_t)(N0 + (lsel & 7)) * TS + ((lsel >> 3) << 4);
        for (int k = 0; k < 4; k++) {
            __syncthreads();                       // prev MMA reads done
            build_tile(S, A + k * 128, (char*)YT, tid);
            __syncthreads();
            #pragma unroll
            for (int nt = 0; nt < 4; nt++) {
                float c0 = 0.f, c1 = 0.f, c2 = 0.f, c3 = 0.f;
                #pragma unroll
                for (int kt = 0; kt < 8; kt++) {
                    uint32_t bh0, bh1, bl0, bl1;
                    uint32_t ba = bbase + nt * (8 * TS) + kt * 32;
                    LDSM2(bh0, bh1, ba);
                    LDSM2(bl0, bl1, ba + THALF);
                    MMA16816(c0, c1, c2, c3, &ah[kt * 4], bh0, bh1);
                    MMA16816(c0, c1, c2, c3, &ah[kt * 4], bl0, bl1);
                    MMA16816(c0, c1, c2, c3, &al[kt * 4], bh0, bh1);
                }
                int j0 = N0 + nt * 8 + ((lane & 3) << 1);
                int code = k + 1;
                if (ADJ[i0 * 68 + j0] == code)           sel[nt][0] = (c0 >= 0.f) ? c0 : 0.2f * c0;
                if (ADJ[i0 * 68 + j0 + 1] == code)       sel[nt][1] = (c1 >= 0.f) ? c1 : 0.2f * c1;
                if (ADJ[(i0 + 8) * 68 + j0] == code)     sel[nt][2] = (c2 >= 0.f) ? c2 : 0.2f * c2;
                if (ADJ[(i0 + 8) * 68 + j0 + 1] == code) sel[nt][3] = (c3 >= 0.f) ? c3 : 0.2f * c3;
            }
        }

        // ===== fragment softmax =====
        float m0 = NEG_BIG, m1 = NEG_BIG;
        #pragma unroll
        for (int nt = 0; nt < 4; nt++) {
            m0 = fmaxf(m0, fmaxf(sel[nt][0], sel[nt][1]));
            m1 = fmaxf(m1, fmaxf(sel[nt][2], sel[nt][3]));
        }
        m0 = fmaxf(m0, __shfl_xor_sync(0xffffffffu, m0, 1));
        m0 = fmaxf(m0, __shfl_xor_sync(0xffffffffu, m0, 2));
        m1 = fmaxf(m1, __shfl_xor_sync(0xffffffffu, m1, 1));
        m1 = fmaxf(m1, __shfl_xor_sync(0xffffffffu, m1, 2));
        if ((lane & 3) == 0) { PA[i0 * 2 + nhalf] = m0; PA[(i0 + 8) * 2 + nhalf] = m1; }
        __syncthreads();
        m0 = fmaxf(PA[i0 * 2], PA[i0 * 2 + 1]);
        m1 = fmaxf(PA[(i0 + 8) * 2], PA[(i0 + 8) * 2 + 1]);
        float s0 = 0.f, s1 = 0.f;
        #pragma unroll
        for (int nt = 0; nt < 4; nt++) {
            sel[nt][0] = __expf(sel[nt][0] - m0); s0 += sel[nt][0];
            sel[nt][1] = __expf(sel[nt][1] - m0); s0 += sel[nt][1];
            sel[nt][2] = __expf(sel[nt][2] - m1); s1 += sel[nt][2];
            sel[nt][3] = __expf(sel[nt][3] - m1); s1 += sel[nt][3];
        }
        s0 += __shfl_xor_sync(0xffffffffu, s0, 1);
        s0 += __shfl_xor_sync(0xffffffffu, s0, 2);
        s1 += __shfl_xor_sync(0xffffffffu, s1, 1);
        s1 += __shfl_xor_sync(0xffffffffu, s1, 2);
        if ((lane & 3) == 0) { PB[i0 * 2 + nhalf] = s0; PB[(i0 + 8) * 2 + nhalf] = s1; }
        __syncthreads();
        float inv0 = 1.f / (PB[i0 * 2] + PB[i0 * 2 + 1]);
        float inv1 = 1.f / (PB[(i0 + 8) * 2] + PB[(i0 + 8) * 2 + 1]);

        // ===== write ATT tile (into Y region, Y dead) =====
        #pragma unroll
        for (int nt = 0; nt < 4; nt++) {
            int j0 = N0 + nt * 8 + ((lane & 3) << 1);
            uint32_t hi, lo;
            cvt_hilo(make_float2(sel[nt][0] * inv0, sel[nt][1] * inv0), hi, lo);
            int off = i0 * ATT_S + j0 * 2;
            *reinterpret_cast<uint32_t*>(YT + off)            = hi;
            *reinterpret_cast<uint32_t*>(YT + ATT_HALF + off) = lo;
            cvt_hilo(make_float2(sel[nt][2] * inv1, sel[nt][3] * inv1), hi, lo);
            off = (i0 + 8) * ATT_S + j0 * 2;
            *reinterpret_cast<uint32_t*>(YT + off)            = hi;
            *reinterpret_cast<uint32_t*>(YT + ATT_HALF + off) = lo;
        }
        __syncthreads();

        // ===== T = att @ S (A from ATT, B = X^T) =====
        {
            uint32_t aah[16], aal[16];
            int m4 = lane >> 3;
            uint32_t abase = YH + (uint32_t)(R0 + (lane & 7) + ((m4 & 1) << 3)) * ATT_S
                           + ((m4 >> 1) << 4);
            #pragma unroll
            for (int kt = 0; kt < 4; kt++) {
                LDSM4(&aah[kt * 4], abase + kt * 32);
                LDSM4(&aal[kt * 4], abase + ATT_HALF + kt * 32);
            }
            const int N0d = nhalf * 64;
            float tc[8][4];
            #pragma unroll
            for (int nt = 0; nt < 8; nt++)
                #pragma unroll
                for (int q = 0; q < 4; q++) tc[nt][q] = 0.f;
            #pragma unroll
            for (int nt = 0; nt < 8; nt++) {
                #pragma unroll
                for (int kt = 0; kt < 4; kt++) {
                    uint32_t bh0, bh1, bl0, bl1;
                    uint32_t ba = XH + (uint32_t)(kt * 16 + lsel) * TS + (uint32_t)(N0d + nt * 8) * 2;
                    LDSM2T(bh0, bh1, ba);
                    LDSM2T(bl0, bl1, ba + THALF);
                    MMA16816(tc[nt][0], tc[nt][1], tc[nt][2], tc[nt][3], &aah[kt * 4], bh0, bh1);
                    MMA16816(tc[nt][0], tc[nt][1], tc[nt][2], tc[nt][3], &aah[kt * 4], bl0, bl1);
                    MMA16816(tc[nt][0], tc[nt][1], tc[nt][2], tc[nt][3], &aal[kt * 4], bh0, bh1);
                }
            }

            // alpha partials
            float pa0 = 0.f, pa1 = 0.f;
            #pragma unroll
            for (int nt = 0; nt < 8; nt++) {
                int d0 = N0d + nt * 8 + ((lane & 3) << 1);
                float2 va = *reinterpret_cast<const float2*>(&V2A[d0]);
                pa0 += tc[nt][0] * va.x + tc[nt][1] * va.y;
                pa1 += tc[nt][2] * va.x + tc[nt][3] * va.y;
            }
            pa0 += __shfl_xor_sync(0xffffffffu, pa0, 1);
            pa0 += __shfl_xor_sync(0xffffffffu, pa0, 2);
            pa1 += __shfl_xor_sync(0xffffffffu, pa1, 1);
            pa1 += __shfl_xor_sync(0xffffffffu, pa1, 2);
            if ((lane & 3) == 0) { PA[i0 * 2 + nhalf] = pa0; PA[(i0 + 8) * 2 + nhalf] = pa1; }
            __syncthreads();
            float al0 = (PA[i0 * 2] + PA[i0 * 2 + 1]) * RSQ;
            float al1 = (PA[(i0 + 8) * 2] + PA[(i0 + 8) * 2 + 1]) * RSQ;

            // blend, write S fp32 + X tile, beta partials
            float pb0 = 0.f, pb1 = 0.f;
            #pragma unroll
            for (int nt = 0; nt < 8; nt++) {
                int d0 = N0d + nt * 8 + ((lane & 3) << 1);
                float2 st = *reinterpret_cast<const float2*>(&STAR[d0]);
                float2 vb = *reinterpret_cast<const float2*>(&V2B[d0]);
                float n0x = (1.f - al0) * tc[nt][0] + al0 * st.x;
                float n0y = (1.f - al0) * tc[nt][1] + al0 * st.y;
                float n1x = (1.f - al1) * tc[nt][2] + al1 * st.x;
                float n1y = (1.f - al1) * tc[nt][3] + al1 * st.y;
                *reinterpret_cast<float2*>(&S[i0 * NPAD + d0])       = make_float2(n0x, n0y);
                *reinterpret_cast<float2*>(&S[(i0 + 8) * NPAD + d0]) = make_float2(n1x, n1y);
                uint32_t hi, lo;
                int off = i0 * TS + d0 * 2;
                cvt_hilo(make_float2(n0x, n0y), hi, lo);
                *reinterpret_cast<uint32_t*>(XT + off)         = hi;
                *reinterpret_cast<uint32_t*>(XT + THALF + off) = lo;
                off = (i0 + 8) * TS + d0 * 2;
                cvt_hilo(make_float2(n1x, n1y), hi, lo);
                *reinterpret_cast<uint32_t*>(XT + off)         = hi;
                *reinterpret_cast<uint32_t*>(XT + THALF + off) = lo;
                pb0 += n0x * vb.x + n0y * vb.y;
                pb1 += n1x * vb.x + n1y * vb.y;
            }
            pb0 += __shfl_xor_sync(0xffffffffu, pb0, 1);
            pb0 += __shfl_xor_sync(0xffffffffu, pb0, 2);
            pb1 += __shfl_xor_sync(0xffffffffu, pb1, 1);
            pb1 += __shfl_xor_sync(0xffffffffu, pb1, 2);
            if ((lane & 3) == 0) { PB[i0 * 2 + nhalf] = pb0; PB[(i0 + 8) * 2 + nhalf] = pb1; }
        }
        __syncthreads();

        if (warp == 0) {
            float b0 = (MS[lane] == 0.f)      ? __int_as_float(0xff800000)
                                              : (PB[lane * 2] + PB[lane * 2 + 1]) * RSQ;
            float b1 = (MS[lane + 32] == 0.f) ? __int_as_float(0xff800000)
                                              : (PB[(lane + 32) * 2] + PB[(lane + 32) * 2 + 1]) * RSQ;
            float m = fmaxf(b0, b1);
            #pragma unroll
            for (int o = 16; o > 0; o >>= 1) m = fmaxf(m, __shfl_xor_sync(0xffffffffu, m, o));
            float e0 = __expf(b0 - m), e1 = __expf(b1 - m);
            float sE = e0 + e1;
            #pragma unroll
            for (int o = 16; o > 0; o >>= 1) sE += __shfl_xor_sync(0xffffffffu, sE, o);
            float inv = 1.f / sE;
            BR[lane] = e0 * inv; BR[lane + 32] = e1 * inv;
        }
        __syncthreads();
        if (tid < 128) {
            float acc = 0.f;
            #pragma unroll 8
            for (int j = 0; j < 64; j++) acc += BR[j] * S[j * NPAD + tid];
            STAR[tid] = acc;
        }
        __syncthreads();
    }

    // ===== gate: C = cat(hidden,S) @ W^T =====
    {
        char* WT = YT;                      // spills 2KB into dead A region
        const uint32_t WTH = YH;
        const int N0g = nhalf * 64;
        float acc[8][4];
        #pragma unroll
        for (int nt = 0; nt < 8; nt++)
            #pragma unroll
            for (int q = 0; q < 4; q++) acc[nt][q] = 0.f;

        for (int chunk = 0; chunk < 4; chunk++) {
            const int c0 = chunk * 64;
            __syncthreads();
            for (int idx = tid; idx < 4096; idx += 256) {
                int o = idx >> 5, p = idx & 31;
                float2 w = __ldg(reinterpret_cast<const float2*>(&wlin[o * 256 + c0 + p * 2]));
                uint32_t hi, lo;
                cvt_hilo(w, hi, lo);
                *reinterpret_cast<uint32_t*>(WT + o * GWS + p * 4)          = hi;
                *reinterpret_cast<uint32_t*>(WT + GWHALF + o * GWS + p * 4) = lo;
            }
            __syncthreads();
            const bool fh = chunk < 2;
            const int cb = fh ? c0 : (c0 - 128);
            const int r0 = i0;
            #pragma unroll
            for (int kt = 0; kt < 4; kt++) {
                uint32_t fah[4], fal[4];
                if (fh) {
                    int cc = cb + kt * 16 + ((lane & 3) << 1);
                    float2 x00 = __ldg(reinterpret_cast<const float2*>(&hg[r0 * 128 + cc]));
                    float2 x10 = __ldg(reinterpret_cast<const float2*>(&hg[(r0 + 8) * 128 + cc]));
                    float2 x01 = __ldg(reinterpret_cast<const float2*>(&hg[r0 * 128 + cc + 8]));
                    float2 x11 = __ldg(reinterpret_cast<const float2*>(&hg[(r0 + 8) * 128 + cc + 8]));
                    cvt_hilo(x00, fah[0], fal[0]);
                    cvt_hilo(x10, fah[1], fal[1]);
                    cvt_hilo(x01, fah[2], fal[2]);
                    cvt_hilo(x11, fah[3], fal[3]);
                } else {
                    int m4 = lane >> 3;
                    uint32_t abase = XH + (uint32_t)(R0 + (lane & 7) + ((m4 & 1) << 3)) * TS
                                   + ((m4 >> 1) << 4) + (uint32_t)(cb + kt * 16) * 2;
                    LDSM4(fah, abase);
                    LDSM4(fal, abase + THALF);
                }
                uint32_t bb = WTH + (uint32_t)(N0g + (lsel & 7)) * GWS + ((lsel >> 3) << 4) + kt * 32;
                #pragma unroll
                for (int nt = 0; nt < 8; nt++) {
                    uint32_t bh0, bh1, bl0, bl1;
                    uint32_t ba = bb + nt * (8 * GWS);
                    LDSM2(bh0, bh1, ba);
                    LDSM2(bl0, bl1, ba + GWHALF);
                    MMA16816(acc[nt][0], acc[nt][1], acc[nt][2], acc[nt][3], fah, bh0, bh1);
                    MMA16816(acc[nt][0], acc[nt][1], acc[nt][2], acc[nt][3], fah, bl0, bl1);
                    MMA16816(acc[nt][0], acc[nt][1], acc[nt][2], acc[nt][3], fal, bh0, bh1);
                }
            }
        }

        float* ob = outp + (size_t)b * (NN * 128);
        const int r0 = i0;
        #pragma unroll
        for (int nt = 0; nt < 8; nt++) {
            int o0 = N0g + nt * 8 + ((lane & 3) << 1);
            float2 h0 = __ldg(reinterpret_cast<const float2*>(&hg[r0 * 128 + o0]));
            float2 s0v = *reinterpret_cast<const float2*>(&S[r0 * NPAD + o0]);
            float2 h1 = __ldg(reinterpret_cast<const float2*>(&hg[(r0 + 8) * 128 + o0]));
            float2 s1v = *reinterpret_cast<const float2*>(&S[(r0 + 8) * NPAD + o0]);
            float g00 = 1.f / (1.f + __expf(-acc[nt][0]));
            float g01 = 1.f / (1.f + __expf(-acc[nt][1]));
            float g10 = 1.f / (1.f + __expf(-acc[nt][2]));
            float g11 = 1.f / (1.f + __expf(-acc[nt][3]));
            float2 r0v, r1v;
            r0v.x = g00 * h0.x + (1.f - g00) * s0v.x;
            r0v.y = g01 * h0.y + (1.f - g01) * s0v.y;
            r1v.x = g10 * h1.x + (1.f - g10) * s1v.x;
            r1v.y = g11 * h1.y + (1.f - g11) * s1v.y;
            *reinterpret_cast<float2*>(&ob[r0 * 128 + o0])       = r0v;
            *reinterpret_cast<float2*>(&ob[(r0 + 8) * 128 + o0]) = r1v;
        }
    }
    if (tid < 128) starp[(size_t)b * 128 + tid] = STAR[tid];
}

extern "C" void kernel_launch(void* const* d_in, const int* in_sizes, int n_in,
                              void* d_out, int out_size) {
    float* outp  = (float*)d_out;
    float* starp = outp + (size_t)NB * NN * 128;

    prep_kernel<<<128, 256>>>((const float*)d_in[7], (const float*)d_in[8],
                              (const float*)d_in[9], (const float*)d_in[10]);
    cudaFuncSetAttribute(star_agg_kernel, cudaFuncAttributeMaxDynamicSharedMemorySize, SM_BYTES);
    star_agg_kernel<<<NB, 256, SM_BYTES>>>(
        (const float*)d_in[0], (const int*)d_in[1], (const float*)d_in[2],
        (const float*)d_in[3], (const float*)d_in[4], (const float*)d_in[5], (const float*)d_in[6],
        (const float*)d_in[11], outp, starp);
}